// round 7
// baseline (speedup 1.0000x reference)
#include <cuda_runtime.h>
#include <cuda_bf16.h>
#include <cuda_fp8.h>
#include <stdint.h>
#include <stddef.h>

#define DIM   1024
#define BQ    2048
#define CC    65536
#define KSEL  8
#define KCAND 32
#define NTILE (CC / 128)        // 512 key tiles per query
#define PER_TILE 8              // candidates kept per (query, tile)

// ---------------- fp8 GEMM geometry ----------------
#define BM 128
#define BN 128
#define BKB 64                  // 64 fp8 bytes of K per chunk
#define NCHUNK (DIM / BKB)      // 16
#define LDSB 80                 // smem row stride in bytes (64 + 16 pad)
#define STAGE_BYTES (2 * BM * LDSB)   // A + B : 20480 B
#define STAGES 3
#define SMEM_DYN (STAGES * STAGE_BYTES)   // 61440
#define SIMS_STRIDE 136         // uint16 elems per sims row (128 + 8 pad); 272B rows, 16B-aligned
#define SMEM_TOP8 35840         // byte offset of per-thread top-8 buffer (sims tile ends at 34816)

// ---------------- scratch (device globals; no allocations allowed) ----------------
static __device__ uint8_t  g_Qf8[(size_t)BQ * DIM];               // 2 MB   (raw query, e4m3)
static __device__ uint8_t  g_Kf8[(size_t)CC * DIM];               // 64 MB  (16*normalized keys, e4m3)
static __device__ float    g_rnorm[CC];                           // 256 KB
static __device__ uint32_t g_part[(size_t)BQ * NTILE * PER_TILE]; // 32 MB  (mono16<<16 | col)
static __device__ int      g_cand[BQ * KCAND];                    // 256 KB

// ---------------- helpers ----------------
__device__ __forceinline__ void cp_async16(void* smem, const void* gmem) {
    uint32_t s = (uint32_t)__cvta_generic_to_shared(smem);
    asm volatile("cp.async.cg.shared.global [%0], [%1], 16;\n" :: "r"(s), "l"(gmem) : "memory");
}
#define CP_COMMIT() asm volatile("cp.async.commit_group;\n" ::: "memory")

// pack 4 floats -> 4 e4m3 bytes (byte i = x[i])
__device__ __forceinline__ uint32_t pack_e4m3x4(float x0, float x1, float x2, float x3) {
    uint16_t lo, hi;
    asm("cvt.rn.satfinite.e4m3x2.f32 %0, %1, %2;" : "=h"(lo) : "f"(x1), "f"(x0));
    asm("cvt.rn.satfinite.e4m3x2.f32 %0, %1, %2;" : "=h"(hi) : "f"(x3), "f"(x2));
    return (uint32_t)lo | ((uint32_t)hi << 16);
}

__device__ __forceinline__ void mma_e4m3(float* d, const uint32_t* a, const uint32_t* b) {
    asm volatile(
        "mma.sync.aligned.m16n8k32.row.col.f32.e4m3.e4m3.f32 "
        "{%0,%1,%2,%3}, {%4,%5,%6,%7}, {%8,%9}, {%0,%1,%2,%3};\n"
        : "+f"(d[0]), "+f"(d[1]), "+f"(d[2]), "+f"(d[3])
        : "r"(a[0]), "r"(a[1]), "r"(a[2]), "r"(a[3]), "r"(b[0]), "r"(b[1]));
}

// float -> bf16 bits -> order-preserving uint16 (larger float => larger uint)
__device__ __forceinline__ uint32_t mono16(float x) {
    uint16_t b = __bfloat16_as_ushort(__float2bfloat16(x));
    return (b & 0x8000u) ? (uint32_t)(uint16_t)~b : (uint32_t)(b | 0x8000u);
}

// insert candidate into sorted-desc v[8] if it beats the tail (rare path)
__device__ __forceinline__ void ins8(uint32_t* v, uint32_t c) {
    if (c > v[7]) {
        v[7] = c;
        #pragma unroll
        for (int j = 7; j > 0; j--)
            if (v[j] > v[j - 1]) { uint32_t tv = v[j]; v[j] = v[j - 1]; v[j - 1] = tv; }
    }
}

// ---------------- prep: query -> e4m3 ----------------
__global__ void prep_q_kernel(const float4* __restrict__ q) {
    int i = blockIdx.x * blockDim.x + threadIdx.x;   // over BQ*DIM/4
    float4 v = q[i];
    ((uint32_t*)g_Qf8)[i] = pack_e4m3x4(v.x, v.y, v.z, v.w);
}

// ---------------- prep: keys -> 16 * normalized e4m3 + inverse norms ----------------
__global__ void prep_keys_kernel(const float* __restrict__ keys) {
    int row = blockIdx.x;
    int t = threadIdx.x, lane = t & 31, w = t >> 5;
    const float4* kr = (const float4*)(keys + (size_t)row * DIM);   // 256 float4 per row
    float4 v = kr[t];
    float ss = v.x*v.x + v.y*v.y + v.z*v.z + v.w*v.w;
    #pragma unroll
    for (int o = 16; o; o >>= 1) ss += __shfl_xor_sync(0xFFFFFFFFu, ss, o);
    __shared__ float sred[8];
    __shared__ float srn;
    if (lane == 0) sred[w] = ss;
    __syncthreads();
    if (t == 0) {
        float tot = 0.f;
        #pragma unroll
        for (int j = 0; j < 8; j++) tot += sred[j];
        float rn = 1.0f / fmaxf(sqrtf(tot), 1e-12f);
        g_rnorm[row] = rn;
        srn = rn * 16.0f;       // scale into e4m3 sweet spot (monotone per-column factor)
    }
    __syncthreads();
    float rn = srn;
    ((uint32_t*)(g_Kf8 + (size_t)row * DIM))[t] =
        pack_e4m3x4(v.x * rn, v.y * rn, v.z * rn, v.w * rn);
}

// ---------------- fp8 GEMM fused with per-tile top-8 selection ----------------
__global__ __launch_bounds__(256, 2) void gemm_kernel() {
    extern __shared__ uint8_t smem[];

    const int tid = threadIdx.x;
    const int m0 = blockIdx.y * BM;
    const int n0 = blockIdx.x * BN;
    const int warp = tid >> 5, lane = tid & 31;
    const int wm = (warp & 1) * 64;     // 2 warps in M (64 rows each)
    const int wn = (warp >> 1) * 32;    // 4 warps in N (32 cols each)

    float acc[4][4][4];
    #pragma unroll
    for (int i = 0; i < 4; i++)
        #pragma unroll
        for (int j = 0; j < 4; j++)
            #pragma unroll
            for (int r = 0; r < 4; r++) acc[i][j][r] = 0.f;

    // stage layout: A rows [0,128) then B rows [0,128), each LDSB bytes
#define LOAD_CHUNK(st, kt) do {                                                        \
        uint8_t* base_ = smem + (st) * STAGE_BYTES;                                    \
        int kb_ = (kt) * BKB;                                                          \
        _Pragma("unroll")                                                              \
        for (int h = 0; h < 4; h++) {                                                  \
            int e_ = tid + (h << 8);          /* 0..1023 */                            \
            int row_ = e_ >> 2, seg_ = e_ & 3;                                         \
            const uint8_t* g_ = (row_ < BM)                                            \
                ? g_Qf8 + (((size_t)(m0 + row_)) << 10) + kb_ + (seg_ << 4)            \
                : g_Kf8 + (((size_t)(n0 + row_ - BM)) << 10) + kb_ + (seg_ << 4);      \
            cp_async16(base_ + row_ * LDSB + (seg_ << 4), g_);                         \
        }                                                                              \
        CP_COMMIT();                                                                   \
    } while (0)

    LOAD_CHUNK(0, 0);
    LOAD_CHUNK(1, 1);
    LOAD_CHUNK(2, 2);

    for (int kt = 0; kt < NCHUNK; kt++) {
        const int st = kt % 3;
        if (kt < NCHUNK - 2)       asm volatile("cp.async.wait_group 2;\n" ::: "memory");
        else if (kt == NCHUNK - 2) asm volatile("cp.async.wait_group 1;\n" ::: "memory");
        else                       asm volatile("cp.async.wait_group 0;\n" ::: "memory");
        __syncthreads();

        const uint8_t* sA = smem + st * STAGE_BYTES;
        const uint8_t* sB = sA + BM * LDSB;

        #pragma unroll
        for (int ks = 0; ks < 2; ks++) {            // two k32 steps per 64B chunk
            const int kb = ks * 32;
            uint32_t a[4][4], bfr[4][2];
            #pragma unroll
            for (int mt = 0; mt < 4; mt++) {
                const uint8_t* p = sA + (wm + mt * 16 + (lane & 15)) * LDSB
                                      + kb + ((lane >> 4) << 4);
                uint32_t ad = (uint32_t)__cvta_generic_to_shared(p);
                asm volatile("ldmatrix.sync.aligned.m8n8.x4.shared.b16 {%0,%1,%2,%3}, [%4];\n"
                             : "=r"(a[mt][0]), "=r"(a[mt][1]), "=r"(a[mt][2]), "=r"(a[mt][3])
                             : "r"(ad));
            }
            #pragma unroll
            for (int np = 0; np < 2; np++) {        // 16 n-rows per x4
                const uint8_t* p = sB + (wn + np * 16 + (lane & 15)) * LDSB
                                      + kb + ((lane >> 4) << 4);
                uint32_t ad = (uint32_t)__cvta_generic_to_shared(p);
                uint32_t r0, r1, r2, r3;
                asm volatile("ldmatrix.sync.aligned.m8n8.x4.shared.b16 {%0,%1,%2,%3}, [%4];\n"
                             : "=r"(r0), "=r"(r1), "=r"(r2), "=r"(r3) : "r"(ad));
                bfr[np * 2][0]     = r0; bfr[np * 2][1]     = r2;
                bfr[np * 2 + 1][0] = r1; bfr[np * 2 + 1][1] = r3;
            }
            #pragma unroll
            for (int mt = 0; mt < 4; mt++)
                #pragma unroll
                for (int nt = 0; nt < 4; nt++)
                    mma_e4m3(acc[mt][nt], a[mt], bfr[nt]);
        }
        __syncthreads();
        if (kt + 3 < NCHUNK) LOAD_CHUNK(st, kt + 3);
    }
#undef LOAD_CHUNK

    // ---- stage sims tile into smem as sortable uint16 (pipeline stages are dead now) ----
    __syncthreads();
    uint16_t* sS = (uint16_t*)smem;     // [128][SIMS_STRIDE]
    #pragma unroll
    for (int mt = 0; mt < 4; mt++) {
        #pragma unroll
        for (int nt = 0; nt < 4; nt++) {
            int r0 = wm + mt * 16 + (lane >> 2);
            int cl = wn + nt * 8 + (lane & 3) * 2;
            uint32_t p0 = mono16(acc[mt][nt][0]) | (mono16(acc[mt][nt][1]) << 16);
            uint32_t p1 = mono16(acc[mt][nt][2]) | (mono16(acc[mt][nt][3]) << 16);
            *(uint32_t*)&sS[r0 * SIMS_STRIDE + cl]       = p0;
            *(uint32_t*)&sS[(r0 + 8) * SIMS_STRIDE + cl] = p1;
        }
    }
    __syncthreads();

    // ---- per-row top-8: 2 threads/row, each scans 64 cols sequentially (no shfl chains) ----
    {
        const int row = tid >> 1;
        const int half = tid & 1;
        const uint4* rp = (const uint4*)&sS[row * SIMS_STRIDE + half * 64];
        const uint32_t cb = (uint32_t)(n0 + half * 64);

        uint32_t v[8];
        #pragma unroll
        for (int j = 0; j < 8; j++) v[j] = 0;

        #pragma unroll
        for (int i = 0; i < 8; i++) {               // 8 x 16B = 64 uint16 vals
            uint4 d = rp[i];
            uint32_t c8 = cb + i * 8;
            ins8(v, (d.x << 16)          | c8);
            ins8(v, (d.x & 0xFFFF0000u)  | (c8 + 1));
            ins8(v, (d.y << 16)          | (c8 + 2));
            ins8(v, (d.y & 0xFFFF0000u)  | (c8 + 3));
            ins8(v, (d.z << 16)          | (c8 + 4));
            ins8(v, (d.z & 0xFFFF0000u)  | (c8 + 5));
            ins8(v, (d.w << 16)          | (c8 + 6));
            ins8(v, (d.w & 0xFFFF0000u)  | (c8 + 7));
        }

        // publish partner halves, then even thread merges (two-pointer over sorted-desc lists)
        uint32_t* sv = (uint32_t*)(smem + SMEM_TOP8);   // 256 threads x 8 = 8 KB
        #pragma unroll
        for (int j = 0; j < 8; j++) sv[tid * 8 + j] = v[j];
        __syncthreads();
        if (half == 0) {
            const uint32_t* bv = &sv[(tid + 1) * 8];
            uint32_t outv[8];
            int ia = 0, ib = 0;
            #pragma unroll
            for (int r = 0; r < 8; r++) {
                uint32_t av = v[ia], bb = bv[ib];
                if (av >= bb) { outv[r] = av; ia++; }
                else          { outv[r] = bb; ib++; }
            }
            uint4* dst = (uint4*)&g_part[((size_t)(m0 + row)) * (NTILE * PER_TILE)
                                         + blockIdx.x * PER_TILE];
            dst[0] = make_uint4(outv[0], outv[1], outv[2], outv[3]);
            dst[1] = make_uint4(outv[4], outv[5], outv[6], outv[7]);
        }
    }
}

// ---------------- merge: per query, top-32 of the 4096 per-tile candidates ----------------
__global__ void merge_kernel() {
    const int q = blockIdx.x;
    const int t = threadIdx.x, lane = t & 31, warp = t >> 5;
    const uint4* p = (const uint4*)(g_part + (size_t)q * (NTILE * PER_TILE));

    // per-thread top-8 (sorted desc) over 16 entries (4 coalesced uint4 loads)
    uint32_t v[8];
    #pragma unroll
    for (int j = 0; j < 8; j++) v[j] = 0;
    #pragma unroll
    for (int j = 0; j < 4; j++) {
        uint4 d = p[t + (j << 8)];
        ins8(v, d.x); ins8(v, d.y); ins8(v, d.z); ins8(v, d.w);
    }

    // warp-local top-32 extraction (head pointer over sorted-desc v[]); no block syncs
    __shared__ uint32_t sw[256];
    int head = 0;
    uint32_t keep = 0;
    for (int r = 0; r < KCAND; r++) {
        uint32_t my = (head < 8) ? v[head] : 0;
        uint32_t b = my;
        #pragma unroll
        for (int o = 16; o; o >>= 1) b = max(b, __shfl_xor_sync(0xFFFFFFFFu, b, o));
        if (b != 0 && my == b) head++;
        if (lane == r) keep = b;
    }
    sw[warp * 32 + lane] = keep;
    __syncthreads();

    // warp 0 merges 8x32 survivors -> final top-32
    if (warp == 0) {
        uint32_t k2[8];
        #pragma unroll
        for (int j = 0; j < 8; j++) k2[j] = sw[lane + (j << 5)];
        uint32_t keep2 = 0;
        for (int r = 0; r < KCAND; r++) {
            uint32_t b = 0;
            #pragma unroll
            for (int j = 0; j < 8; j++) b = max(b, k2[j]);
            #pragma unroll
            for (int o = 16; o; o >>= 1) b = max(b, __shfl_xor_sync(0xFFFFFFFFu, b, o));
            #pragma unroll
            for (int j = 0; j < 8; j++)
                if (k2[j] == b) k2[j] = 0;
            if (lane == r) keep2 = b;
        }
        g_cand[q * KCAND + lane] = (int)(keep2 & 0xFFFFu);
    }
}

// ---------------- usage init: out_usage = memory_usage ----------------
__global__ void usage_init_kernel(const float* __restrict__ u, float* __restrict__ out_u) {
    int i = blockIdx.x * blockDim.x + threadIdx.x;
    out_u[i] = u[i];
}

// ---------------- exact fp32 rescore of 32 candidates + top-8 + gather + counts ----------------
__global__ void rescore_gather_kernel(const float* __restrict__ q,
                                      const float* __restrict__ keys,
                                      const float* __restrict__ vals,
                                      float* __restrict__ out_k,
                                      float* __restrict__ out_v,
                                      float* __restrict__ out_u) {
    const int b = blockIdx.x;
    const int t = threadIdx.x, lane = t & 31, w = t >> 5;
    __shared__ float qs[DIM];
    __shared__ float simv[KCAND];
    __shared__ int   simi[KCAND];
    __shared__ int   topi[KSEL];

    ((float4*)qs)[t] = ((const float4*)(q + (size_t)b * DIM))[t];
    __syncthreads();

    #pragma unroll
    for (int jj = 0; jj < 4; jj++) {
        int j = w * 4 + jj;
        int c = g_cand[b * KCAND + j];
        const float* kr = keys + (size_t)c * DIM;
        float s = 0.f;
        #pragma unroll 8
        for (int i = lane; i < DIM; i += 32) s = fmaf(qs[i], kr[i], s);
        #pragma unroll
        for (int o = 16; o; o >>= 1) s += __shfl_xor_sync(0xFFFFFFFFu, s, o);
        if (lane == 0) { simv[j] = s * g_rnorm[c]; simi[j] = c; }
    }
    __syncthreads();

    if (t == 0) {
        unsigned used = 0;
        for (int r = 0; r < KSEL; r++) {
            int best = -1;
            for (int j = 0; j < KCAND; j++) {
                if (used & (1u << j)) continue;
                if (best < 0 || simv[j] > simv[best] ||
                    (simv[j] == simv[best] && simi[j] < simi[best])) best = j;
            }
            used |= 1u << best;
            topi[r] = simi[best];
        }
    }
    __syncthreads();

    for (int r = 0; r < KSEL; r++) {
        int c = topi[r];
        const float4* sk = (const float4*)(keys + (size_t)c * DIM);
        const float4* sw = (const float4*)(vals + (size_t)c * DIM);
        float4* dk = (float4*)(out_k + ((size_t)b * KSEL + r) * DIM);
        float4* dv = (float4*)(out_v + ((size_t)b * KSEL + r) * DIM);
        dk[t] = sk[t];
        dv[t] = sw[t];
    }
    if (t < KSEL) atomicAdd(&out_u[topi[t]], 1.0f);
}

// ---------------- launch ----------------
extern "C" void kernel_launch(void* const* d_in, const int* in_sizes, int n_in,
                              void* d_out, int out_size) {
    const float* query  = (const float*)d_in[0];
    const float* keys   = (const float*)d_in[1];
    const float* values = (const float*)d_in[2];
    const float* usage  = (const float*)d_in[3];
    // d_in[4] = k (fixed to 8 by problem shape / out_size)

    float* out       = (float*)d_out;
    float* out_keys  = out;
    float* out_vals  = out + (size_t)BQ * KSEL * DIM;
    float* out_usage = out + (size_t)2 * BQ * KSEL * DIM;

    cudaFuncSetAttribute(gemm_kernel, cudaFuncAttributeMaxDynamicSharedMemorySize, SMEM_DYN);

    prep_q_kernel<<<(BQ * DIM / 4) / 256, 256>>>((const float4*)query);
    prep_keys_kernel<<<CC, 256>>>(keys);

    dim3 ggrid(CC / BN, BQ / BM);       // (512, 16)
    gemm_kernel<<<ggrid, 256, SMEM_DYN>>>();

    merge_kernel<<<BQ, 256>>>();
    usage_init_kernel<<<CC / 256, 256>>>(usage, out_usage);
    rescore_gather_kernel<<<BQ, 256>>>(query, keys, values, out_keys, out_vals, out_usage);
}

// round 10
// speedup vs baseline: 1.0881x; 1.0881x over previous
#include <cuda_runtime.h>
#include <cuda_bf16.h>
#include <cuda_fp8.h>
#include <stdint.h>
#include <stddef.h>

#define DIM   1024
#define BQ    2048
#define CC    65536
#define KSEL  8
#define KCAND 32

// ---------------- fp8 GEMM geometry ----------------
#define BM 128
#define BN 128
#define BKB 64                  // 64 fp8 bytes of K per chunk
#define NCHUNK (DIM / BKB)      // 16
#define LDSB 80                 // smem row stride in bytes (64 + 16 pad)
#define STAGE_BYTES (2 * BM * LDSB)   // A + B : 20480 B
#define STAGES 3
#define SMEM_DYN (STAGES * STAGE_BYTES)   // 61440

// ---------------- scratch (device globals; no allocations allowed) ----------------
static __device__ uint8_t       g_Qf8[(size_t)BQ * DIM];     // 2 MB   (raw query, e4m3)
static __device__ uint8_t       g_Kf8[(size_t)CC * DIM];     // 64 MB  (16*normalized keys, e4m3)
static __device__ float         g_rnorm[CC];                 // 256 KB
static __device__ __nv_bfloat16 g_S[(size_t)BQ * CC];        // 256 MB (bf16 sims, scaled)
static __device__ int           g_cand[BQ * KCAND];          // 256 KB

// ---------------- helpers ----------------
__device__ __forceinline__ void cp_async16(void* smem, const void* gmem) {
    uint32_t s = (uint32_t)__cvta_generic_to_shared(smem);
    asm volatile("cp.async.cg.shared.global [%0], [%1], 16;\n" :: "r"(s), "l"(gmem) : "memory");
}
#define CP_COMMIT() asm volatile("cp.async.commit_group;\n" ::: "memory")

// pack 4 floats -> 4 e4m3 bytes (byte i = x[i])
__device__ __forceinline__ uint32_t pack_e4m3x4(float x0, float x1, float x2, float x3) {
    uint16_t lo, hi;
    asm("cvt.rn.satfinite.e4m3x2.f32 %0, %1, %2;" : "=h"(lo) : "f"(x1), "f"(x0));
    asm("cvt.rn.satfinite.e4m3x2.f32 %0, %1, %2;" : "=h"(hi) : "f"(x3), "f"(x2));
    return (uint32_t)lo | ((uint32_t)hi << 16);
}

__device__ __forceinline__ void mma_e4m3(float* d, const uint32_t* a, const uint32_t* b) {
    asm volatile(
        "mma.sync.aligned.m16n8k32.row.col.f32.e4m3.e4m3.f32 "
        "{%0,%1,%2,%3}, {%4,%5,%6,%7}, {%8,%9}, {%0,%1,%2,%3};\n"
        : "+f"(d[0]), "+f"(d[1]), "+f"(d[2]), "+f"(d[3])
        : "r"(a[0]), "r"(a[1]), "r"(a[2]), "r"(a[3]), "r"(b[0]), "r"(b[1]));
}

// float (exact bf16 value) -> order-preserving uint16 (larger float => larger uint)
__device__ __forceinline__ uint32_t mono16f(float x) {
    uint16_t b = __bfloat16_as_ushort(__float2bfloat16(x));
    return (b & 0x8000u) ? (uint32_t)(uint16_t)~b : (uint32_t)(b | 0x8000u);
}

// ---------------- prep: query -> e4m3 ----------------
__global__ void prep_q_kernel(const float4* __restrict__ q) {
    int i = blockIdx.x * blockDim.x + threadIdx.x;   // over BQ*DIM/4
    float4 v = q[i];
    ((uint32_t*)g_Qf8)[i] = pack_e4m3x4(v.x, v.y, v.z, v.w);
}

// ---------------- prep: keys -> 16 * normalized e4m3 + inverse norms ----------------
__global__ void prep_keys_kernel(const float* __restrict__ keys) {
    int row = blockIdx.x;
    int t = threadIdx.x, lane = t & 31, w = t >> 5;
    const float4* kr = (const float4*)(keys + (size_t)row * DIM);   // 256 float4 per row
    float4 v = kr[t];
    float ss = v.x*v.x + v.y*v.y + v.z*v.z + v.w*v.w;
    #pragma unroll
    for (int o = 16; o; o >>= 1) ss += __shfl_xor_sync(0xFFFFFFFFu, ss, o);
    __shared__ float sred[8];
    __shared__ float srn;
    if (lane == 0) sred[w] = ss;
    __syncthreads();
    if (t == 0) {
        float tot = 0.f;
        #pragma unroll
        for (int j = 0; j < 8; j++) tot += sred[j];
        float rn = 1.0f / fmaxf(sqrtf(tot), 1e-12f);
        g_rnorm[row] = rn;
        srn = rn * 16.0f;       // scale into e4m3 sweet spot (monotone per-column factor)
    }
    __syncthreads();
    float rn = srn;
    ((uint32_t*)(g_Kf8 + (size_t)row * DIM))[t] =
        pack_e4m3x4(v.x * rn, v.y * rn, v.z * rn, v.w * rn);
}

// ---------------- fp8 GEMM: S[b,c] = bf16( Qf8[b,:] . Kf8[c,:] ) ----------------
__global__ __launch_bounds__(256, 2) void gemm_kernel() {
    extern __shared__ uint8_t smem[];

    const int tid = threadIdx.x;
    const int m0 = blockIdx.y * BM;
    const int n0 = blockIdx.x * BN;
    const int warp = tid >> 5, lane = tid & 31;
    const int wm = (warp & 1) * 64;     // 2 warps in M (64 rows each)
    const int wn = (warp >> 1) * 32;    // 4 warps in N (32 cols each)

    float acc[4][4][4];
    #pragma unroll
    for (int i = 0; i < 4; i++)
        #pragma unroll
        for (int j = 0; j < 4; j++)
            #pragma unroll
            for (int r = 0; r < 4; r++) acc[i][j][r] = 0.f;

    // stage layout: A rows [0,128) then B rows [0,128), each LDSB bytes
#define LOAD_CHUNK(st, kt) do {                                                        \
        uint8_t* base_ = smem + (st) * STAGE_BYTES;                                    \
        int kb_ = (kt) * BKB;                                                          \
        _Pragma("unroll")                                                              \
        for (int h = 0; h < 4; h++) {                                                  \
            int e_ = tid + (h << 8);          /* 0..1023 */                            \
            int row_ = e_ >> 2, seg_ = e_ & 3;                                         \
            const uint8_t* g_ = (row_ < BM)                                            \
                ? g_Qf8 + (((size_t)(m0 + row_)) << 10) + kb_ + (seg_ << 4)            \
                : g_Kf8 + (((size_t)(n0 + row_ - BM)) << 10) + kb_ + (seg_ << 4);      \
            cp_async16(base_ + row_ * LDSB + (seg_ << 4), g_);                         \
        }                                                                              \
        CP_COMMIT();                                                                   \
    } while (0)

    LOAD_CHUNK(0, 0);
    LOAD_CHUNK(1, 1);
    LOAD_CHUNK(2, 2);

    for (int kt = 0; kt < NCHUNK; kt++) {
        const int st = kt % 3;
        if (kt < NCHUNK - 2)       asm volatile("cp.async.wait_group 2;\n" ::: "memory");
        else if (kt == NCHUNK - 2) asm volatile("cp.async.wait_group 1;\n" ::: "memory");
        else                       asm volatile("cp.async.wait_group 0;\n" ::: "memory");
        __syncthreads();

        const uint8_t* sA = smem + st * STAGE_BYTES;
        const uint8_t* sB = sA + BM * LDSB;

        #pragma unroll
        for (int ks = 0; ks < 2; ks++) {            // two k32 steps per 64B chunk
            const int kb = ks * 32;
            uint32_t a[4][4], bfr[4][2];
            #pragma unroll
            for (int mt = 0; mt < 4; mt++) {
                const uint8_t* p = sA + (wm + mt * 16 + (lane & 15)) * LDSB
                                      + kb + ((lane >> 4) << 4);
                uint32_t ad = (uint32_t)__cvta_generic_to_shared(p);
                asm volatile("ldmatrix.sync.aligned.m8n8.x4.shared.b16 {%0,%1,%2,%3}, [%4];\n"
                             : "=r"(a[mt][0]), "=r"(a[mt][1]), "=r"(a[mt][2]), "=r"(a[mt][3])
                             : "r"(ad));
            }
            #pragma unroll
            for (int np = 0; np < 2; np++) {        // 16 n-rows per x4
                const uint8_t* p = sB + (wn + np * 16 + (lane & 15)) * LDSB
                                      + kb + ((lane >> 4) << 4);
                uint32_t ad = (uint32_t)__cvta_generic_to_shared(p);
                uint32_t r0, r1, r2, r3;
                asm volatile("ldmatrix.sync.aligned.m8n8.x4.shared.b16 {%0,%1,%2,%3}, [%4];\n"
                             : "=r"(r0), "=r"(r1), "=r"(r2), "=r"(r3) : "r"(ad));
                bfr[np * 2][0]     = r0; bfr[np * 2][1]     = r2;
                bfr[np * 2 + 1][0] = r1; bfr[np * 2 + 1][1] = r3;
            }
            #pragma unroll
            for (int mt = 0; mt < 4; mt++)
                #pragma unroll
                for (int nt = 0; nt < 4; nt++)
                    mma_e4m3(acc[mt][nt], a[mt], bfr[nt]);
        }
        __syncthreads();
        if (kt + 3 < NCHUNK) LOAD_CHUNK(st, kt + 3);
    }
#undef LOAD_CHUNK

    // epilogue: store bf16 sims (keys pre-scaled; no per-column factor needed)
    #pragma unroll
    for (int mt = 0; mt < 4; mt++) {
        #pragma unroll
        for (int nt = 0; nt < 4; nt++) {
            int r0 = m0 + wm + mt * 16 + (lane >> 2);
            int cl = n0 + wn + nt * 8 + (lane & 3) * 2;
            size_t base = (size_t)r0 * CC + cl;
            *(__nv_bfloat162*)&g_S[base] =
                __floats2bfloat162_rn(acc[mt][nt][0], acc[mt][nt][1]);
            *(__nv_bfloat162*)&g_S[base + (size_t)8 * CC] =
                __floats2bfloat162_rn(acc[mt][nt][2], acc[mt][nt][3]);
        }
    }
}

// ---------------- candidate selection: per query, top-32 of the bf16 sims ----------------
__global__ void select_kernel() {
    const int q = blockIdx.x;
    const int t = threadIdx.x, lane = t & 31, warp = t >> 5;
    const uint4* row = (const uint4*)(g_S + (size_t)q * CC);

    // ---- per-thread top-8 scan over a strided 256-value chunk (identical to round 5) ----
    float v[8]; int id[8];
    #pragma unroll
    for (int j = 0; j < 8; j++) { v[j] = -3e38f; id[j] = -1; }

    for (int i = 0; i < CC / 2048; i++) {           // 32 iterations, 8 bf16 per iter
        union { uint4 u; __nv_bfloat162 h[4]; } d;
        d.u = row[(i << 8) + t];
        __nv_bfloat162 m01 = __hmax2(d.h[0], d.h[1]);
        __nv_bfloat162 m23 = __hmax2(d.h[2], d.h[3]);
        __nv_bfloat162 mm  = __hmax2(m01, m23);
        float mx = fmaxf(__bfloat162float(__low2bfloat16(mm)),
                         __bfloat162float(__high2bfloat16(mm)));
        if (mx > v[7]) {
            int base = ((i << 8) + t) << 3;
            float f[8];
            #pragma unroll
            for (int p = 0; p < 4; p++) {
                f[p * 2]     = __bfloat162float(__low2bfloat16(d.h[p]));
                f[p * 2 + 1] = __bfloat162float(__high2bfloat16(d.h[p]));
            }
            #pragma unroll
            for (int e = 0; e < 8; e++) {
                if (f[e] > v[7]) {
                    v[7] = f[e]; id[7] = base + e;
                    #pragma unroll
                    for (int j = 7; j > 0; j--)
                        if (v[j] > v[j - 1]) {
                            float tv = v[j]; v[j] = v[j - 1]; v[j - 1] = tv;
                            int ti = id[j]; id[j] = id[j - 1]; id[j - 1] = ti;
                        }
                }
            }
        }
    }

    // ---- pack (value, idx) -> globally-unique sortable uint32; sorted desc already ----
    uint32_t pk[8];
    #pragma unroll
    for (int j = 0; j < 8; j++)
        pk[j] = (mono16f(v[j]) << 16) | (uint32_t)(id[j] & 0xFFFF);

    // ---- warp-local top-32 extraction (head pointer, no block syncs) ----
    __shared__ uint32_t sw[256];
    int head = 0;
    uint32_t keep = 0;
    for (int r = 0; r < KCAND; r++) {
        uint32_t my = (head < 8) ? pk[head] : 0;
        uint32_t b = my;
        #pragma unroll
        for (int o = 16; o; o >>= 1) b = max(b, __shfl_xor_sync(0xFFFFFFFFu, b, o));
        if (b != 0 && my == b) head++;              // packed values are unique -> one winner
        if (lane == r) keep = b;
    }
    sw[warp * 32 + lane] = keep;
    __syncthreads();

    // ---- warp 0 merges 8x32 survivors -> final top-32 ----
    if (warp == 0) {
        uint32_t k2[8];
        #pragma unroll
        for (int j = 0; j < 8; j++) k2[j] = sw[lane + (j << 5)];
        uint32_t keep2 = 0;
        for (int r = 0; r < KCAND; r++) {
            uint32_t b = 0;
            #pragma unroll
            for (int j = 0; j < 8; j++) b = max(b, k2[j]);
            #pragma unroll
            for (int o = 16; o; o >>= 1) b = max(b, __shfl_xor_sync(0xFFFFFFFFu, b, o));
            #pragma unroll
            for (int j = 0; j < 8; j++)
                if (k2[j] == b) k2[j] = 0;
            if (lane == r) keep2 = b;
        }
        g_cand[q * KCAND + lane] = (int)(keep2 & 0xFFFFu);
    }
}

// ---------------- usage init: out_usage = memory_usage ----------------
__global__ void usage_init_kernel(const float* __restrict__ u, float* __restrict__ out_u) {
    int i = blockIdx.x * blockDim.x + threadIdx.x;
    out_u[i] = u[i];
}

// ---------------- exact fp32 rescore of 32 candidates + top-8 + gather + counts ----------------
__global__ void rescore_gather_kernel(const float* __restrict__ q,
                                      const float* __restrict__ keys,
                                      const float* __restrict__ vals,
                                      float* __restrict__ out_k,
                                      float* __restrict__ out_v,
                                      float* __restrict__ out_u) {
    const int b = blockIdx.x;
    const int t = threadIdx.x, lane = t & 31, w = t >> 5;
    __shared__ float qs[DIM];
    __shared__ float simv[KCAND];
    __shared__ int   simi[KCAND];
    __shared__ int   topi[KSEL];

    ((float4*)qs)[t] = ((const float4*)(q + (size_t)b * DIM))[t];
    __syncthreads();

    #pragma unroll
    for (int jj = 0; jj < 4; jj++) {
        int j = w * 4 + jj;
        int c = g_cand[b * KCAND + j];
        const float* kr = keys + (size_t)c * DIM;
        float s = 0.f;
        #pragma unroll 8
        for (int i = lane; i < DIM; i += 32) s = fmaf(qs[i], kr[i], s);
        #pragma unroll
        for (int o = 16; o; o >>= 1) s += __shfl_xor_sync(0xFFFFFFFFu, s, o);
        if (lane == 0) { simv[j] = s * g_rnorm[c]; simi[j] = c; }
    }
    __syncthreads();

    if (t == 0) {
        unsigned used = 0;
        for (int r = 0; r < KSEL; r++) {
            int best = -1;
            for (int j = 0; j < KCAND; j++) {
                if (used & (1u << j)) continue;
                if (best < 0 || simv[j] > simv[best] ||
                    (simv[j] == simv[best] && simi[j] < simi[best])) best = j;
            }
            used |= 1u << best;
            topi[r] = simi[best];
        }
    }
    __syncthreads();

    for (int r = 0; r < KSEL; r++) {
        int c = topi[r];
        const float4* sk = (const float4*)(keys + (size_t)c * DIM);
        const float4* sv2 = (const float4*)(vals + (size_t)c * DIM);
        float4* dk = (float4*)(out_k + ((size_t)b * KSEL + r) * DIM);
        float4* dv = (float4*)(out_v + ((size_t)b * KSEL + r) * DIM);
        dk[t] = sk[t];
        dv[t] = sv2[t];
    }
    if (t < KSEL) atomicAdd(&out_u[topi[t]], 1.0f);
}

// ---------------- launch ----------------
extern "C" void kernel_launch(void* const* d_in, const int* in_sizes, int n_in,
                              void* d_out, int out_size) {
    const float* query  = (const float*)d_in[0];
    const float* keys   = (const float*)d_in[1];
    const float* values = (const float*)d_in[2];
    const float* usage  = (const float*)d_in[3];
    // d_in[4] = k (fixed to 8 by problem shape / out_size)

    float* out       = (float*)d_out;
    float* out_keys  = out;
    float* out_vals  = out + (size_t)BQ * KSEL * DIM;
    float* out_usage = out + (size_t)2 * BQ * KSEL * DIM;

    cudaFuncSetAttribute(gemm_kernel, cudaFuncAttributeMaxDynamicSharedMemorySize, SMEM_DYN);

    prep_q_kernel<<<(BQ * DIM / 4) / 256, 256>>>((const float4*)query);
    prep_keys_kernel<<<CC, 256>>>(keys);

    dim3 ggrid(CC / BN, BQ / BM);       // (512, 16)
    gemm_kernel<<<ggrid, 256, SMEM_DYN>>>();

    select_kernel<<<BQ, 256>>>();
    usage_init_kernel<<<CC / 256, 256>>>(usage, out_usage);
    rescore_gather_kernel<<<BQ, 256>>>(query, keys, values, out_keys, out_vals, out_usage);
}

// round 11
// speedup vs baseline: 1.3382x; 1.2298x over previous
#include <cuda_runtime.h>
#include <cuda_bf16.h>
#include <cuda_fp8.h>
#include <stdint.h>
#include <stddef.h>

#define DIM   1024
#define BQ    2048
#define CC    65536
#define KSEL  8
#define KCAND 32
#define NTILE (CC / 128)        // 512 col-tiles of width 128

// ---------------- fp8 GEMM geometry ----------------
#define BM 128
#define BN 128
#define BKB 64                  // 64 fp8 bytes of K per chunk
#define NCHUNK (DIM / BKB)      // 16
#define LDSB 80                 // smem row stride in bytes (64 + 16 pad)
#define STAGE_BYTES (2 * BM * LDSB)   // A + B : 20480 B
#define STAGES 3
#define SMEM_DYN (STAGES * STAGE_BYTES)   // 61440

// ---------------- scratch (device globals; no allocations allowed) ----------------
static __device__ uint8_t       g_Qf8[(size_t)BQ * DIM];     // 2 MB   (raw query, e4m3)
static __device__ uint8_t       g_Kf8[(size_t)CC * DIM];     // 64 MB  (16*normalized keys, e4m3)
static __device__ float         g_rnorm[CC];                 // 256 KB
static __device__ __nv_bfloat16 g_S[(size_t)BQ * CC];        // 256 MB (bf16 sims, scaled)
static __device__ uint16_t      g_tmax[(size_t)BQ * NTILE];  // 2 MB   (per row/tile max, mono16)
static __device__ int           g_cand[BQ * KCAND];          // 256 KB

// ---------------- helpers ----------------
__device__ __forceinline__ void cp_async16(void* smem, const void* gmem) {
    uint32_t s = (uint32_t)__cvta_generic_to_shared(smem);
    asm volatile("cp.async.cg.shared.global [%0], [%1], 16;\n" :: "r"(s), "l"(gmem) : "memory");
}
#define CP_COMMIT() asm volatile("cp.async.commit_group;\n" ::: "memory")

// pack 4 floats -> 4 e4m3 bytes (byte i = x[i])
__device__ __forceinline__ uint32_t pack_e4m3x4(float x0, float x1, float x2, float x3) {
    uint16_t lo, hi;
    asm("cvt.rn.satfinite.e4m3x2.f32 %0, %1, %2;" : "=h"(lo) : "f"(x1), "f"(x0));
    asm("cvt.rn.satfinite.e4m3x2.f32 %0, %1, %2;" : "=h"(hi) : "f"(x3), "f"(x2));
    return (uint32_t)lo | ((uint32_t)hi << 16);
}

__device__ __forceinline__ void mma_e4m3(float* d, const uint32_t* a, const uint32_t* b) {
    asm volatile(
        "mma.sync.aligned.m16n8k32.row.col.f32.e4m3.e4m3.f32 "
        "{%0,%1,%2,%3}, {%4,%5,%6,%7}, {%8,%9}, {%0,%1,%2,%3};\n"
        : "+f"(d[0]), "+f"(d[1]), "+f"(d[2]), "+f"(d[3])
        : "r"(a[0]), "r"(a[1]), "r"(a[2]), "r"(a[3]), "r"(b[0]), "r"(b[1]));
}

// float -> bf16(rn) bits -> order-preserving uint16 (larger float => larger uint)
__device__ __forceinline__ uint32_t mono16f(float x) {
    uint16_t b = __bfloat16_as_ushort(__float2bfloat16(x));
    return (b & 0x8000u) ? (uint32_t)(uint16_t)~b : (uint32_t)(b | 0x8000u);
}
// bf16 raw bits -> order-preserving uint16 (same mapping as mono16f on stored values)
__device__ __forceinline__ uint32_t mono16b(uint32_t b) {
    return (b & 0x8000u) ? ((uint32_t)(uint16_t)~b) : (b | 0x8000u);
}

// insert into sorted-desc reg array v[8] (compile-time indices only; rare true branch)
__device__ __forceinline__ void ins8(uint32_t* v, uint32_t c) {
    if (c > v[7]) {
        v[7] = c;
        #pragma unroll
        for (int j = 7; j > 0; j--)
            if (v[j] > v[j - 1]) { uint32_t tv = v[j]; v[j] = v[j - 1]; v[j - 1] = tv; }
    }
}

// ---------------- prep: query -> e4m3 ----------------
__global__ void prep_q_kernel(const float4* __restrict__ q) {
    int i = blockIdx.x * blockDim.x + threadIdx.x;   // over BQ*DIM/4
    float4 v = q[i];
    ((uint32_t*)g_Qf8)[i] = pack_e4m3x4(v.x, v.y, v.z, v.w);
}

// ---------------- prep: keys -> 16 * normalized e4m3 + inverse norms ----------------
__global__ void prep_keys_kernel(const float* __restrict__ keys) {
    int row = blockIdx.x;
    int t = threadIdx.x, lane = t & 31, w = t >> 5;
    const float4* kr = (const float4*)(keys + (size_t)row * DIM);   // 256 float4 per row
    float4 v = kr[t];
    float ss = v.x*v.x + v.y*v.y + v.z*v.z + v.w*v.w;
    #pragma unroll
    for (int o = 16; o; o >>= 1) ss += __shfl_xor_sync(0xFFFFFFFFu, ss, o);
    __shared__ float sred[8];
    __shared__ float srn;
    if (lane == 0) sred[w] = ss;
    __syncthreads();
    if (t == 0) {
        float tot = 0.f;
        #pragma unroll
        for (int j = 0; j < 8; j++) tot += sred[j];
        float rn = 1.0f / fmaxf(sqrtf(tot), 1e-12f);
        g_rnorm[row] = rn;
        srn = rn * 16.0f;       // scale into e4m3 sweet spot (monotone per-column factor)
    }
    __syncthreads();
    float rn = srn;
    ((uint32_t*)(g_Kf8 + (size_t)row * DIM))[t] =
        pack_e4m3x4(v.x * rn, v.y * rn, v.z * rn, v.w * rn);
}

// ---------------- fp8 GEMM: S[b,c] = bf16( Qf8[b,:] . Kf8[c,:] ), + per-row tile max ----
__global__ __launch_bounds__(256, 2) void gemm_kernel() {
    extern __shared__ uint8_t smem[];

    const int tid = threadIdx.x;
    const int m0 = blockIdx.y * BM;
    const int n0 = blockIdx.x * BN;
    const int warp = tid >> 5, lane = tid & 31;
    const int wm = (warp & 1) * 64;     // 2 warps in M (64 rows each)
    const int wn = (warp >> 1) * 32;    // 4 warps in N (32 cols each)

    float acc[4][4][4];
    #pragma unroll
    for (int i = 0; i < 4; i++)
        #pragma unroll
        for (int j = 0; j < 4; j++)
            #pragma unroll
            for (int r = 0; r < 4; r++) acc[i][j][r] = 0.f;

    // stage layout: A rows [0,128) then B rows [0,128), each LDSB bytes
#define LOAD_CHUNK(st, kt) do {                                                        \
        uint8_t* base_ = smem + (st) * STAGE_BYTES;                                    \
        int kb_ = (kt) * BKB;                                                          \
        _Pragma("unroll")                                                              \
        for (int h = 0; h < 4; h++) {                                                  \
            int e_ = tid + (h << 8);          /* 0..1023 */                            \
            int row_ = e_ >> 2, seg_ = e_ & 3;                                         \
            const uint8_t* g_ = (row_ < BM)                                            \
                ? g_Qf8 + (((size_t)(m0 + row_)) << 10) + kb_ + (seg_ << 4)            \
                : g_Kf8 + (((size_t)(n0 + row_ - BM)) << 10) + kb_ + (seg_ << 4);      \
            cp_async16(base_ + row_ * LDSB + (seg_ << 4), g_);                         \
        }                                                                              \
        CP_COMMIT();                                                                   \
    } while (0)

    LOAD_CHUNK(0, 0);
    LOAD_CHUNK(1, 1);
    LOAD_CHUNK(2, 2);

    for (int kt = 0; kt < NCHUNK; kt++) {
        const int st = kt % 3;
        if (kt < NCHUNK - 2)       asm volatile("cp.async.wait_group 2;\n" ::: "memory");
        else if (kt == NCHUNK - 2) asm volatile("cp.async.wait_group 1;\n" ::: "memory");
        else                       asm volatile("cp.async.wait_group 0;\n" ::: "memory");
        __syncthreads();

        const uint8_t* sA = smem + st * STAGE_BYTES;
        const uint8_t* sB = sA + BM * LDSB;

        #pragma unroll
        for (int ks = 0; ks < 2; ks++) {            // two k32 steps per 64B chunk
            const int kb = ks * 32;
            uint32_t a[4][4], bfr[4][2];
            #pragma unroll
            for (int mt = 0; mt < 4; mt++) {
                const uint8_t* p = sA + (wm + mt * 16 + (lane & 15)) * LDSB
                                      + kb + ((lane >> 4) << 4);
                uint32_t ad = (uint32_t)__cvta_generic_to_shared(p);
                asm volatile("ldmatrix.sync.aligned.m8n8.x4.shared.b16 {%0,%1,%2,%3}, [%4];\n"
                             : "=r"(a[mt][0]), "=r"(a[mt][1]), "=r"(a[mt][2]), "=r"(a[mt][3])
                             : "r"(ad));
            }
            #pragma unroll
            for (int np = 0; np < 2; np++) {        // 16 n-rows per x4
                const uint8_t* p = sB + (wn + np * 16 + (lane & 15)) * LDSB
                                      + kb + ((lane >> 4) << 4);
                uint32_t ad = (uint32_t)__cvta_generic_to_shared(p);
                uint32_t r0, r1, r2, r3;
                asm volatile("ldmatrix.sync.aligned.m8n8.x4.shared.b16 {%0,%1,%2,%3}, [%4];\n"
                             : "=r"(r0), "=r"(r1), "=r"(r2), "=r"(r3) : "r"(ad));
                bfr[np * 2][0]     = r0; bfr[np * 2][1]     = r2;
                bfr[np * 2 + 1][0] = r1; bfr[np * 2 + 1][1] = r3;
            }
            #pragma unroll
            for (int mt = 0; mt < 4; mt++)
                #pragma unroll
                for (int nt = 0; nt < 4; nt++)
                    mma_e4m3(acc[mt][nt], a[mt], bfr[nt]);
        }
        __syncthreads();
        if (kt + 3 < NCHUNK) LOAD_CHUNK(st, kt + 3);
    }
#undef LOAD_CHUNK

    // ---- epilogue 1: store bf16 sims ----
    #pragma unroll
    for (int mt = 0; mt < 4; mt++) {
        #pragma unroll
        for (int nt = 0; nt < 4; nt++) {
            int r0 = m0 + wm + mt * 16 + (lane >> 2);
            int cl = n0 + wn + nt * 8 + (lane & 3) * 2;
            size_t base = (size_t)r0 * CC + cl;
            *(__nv_bfloat162*)&g_S[base] =
                __floats2bfloat162_rn(acc[mt][nt][0], acc[mt][nt][1]);
            *(__nv_bfloat162*)&g_S[base + (size_t)8 * CC] =
                __floats2bfloat162_rn(acc[mt][nt][2], acc[mt][nt][3]);
        }
    }

    // ---- epilogue 2: per-row max over this CTA's 128 cols -> g_tmax (reduction only) ----
    float* srow = (float*)smem;         // [128][4] floats = 2 KB (stages are dead)
    #pragma unroll
    for (int mt = 0; mt < 4; mt++) {
        #pragma unroll
        for (int h = 0; h < 2; h++) {   // h=0: row r0, h=1: row r0+8
            float m = fmaxf(acc[mt][0][2*h], acc[mt][0][2*h+1]);
            #pragma unroll
            for (int nt = 1; nt < 4; nt++)
                m = fmaxf(m, fmaxf(acc[mt][nt][2*h], acc[mt][nt][2*h+1]));
            // max over the 4 threads sharing this row (consecutive lanes)
            m = fmaxf(m, __shfl_xor_sync(0xFFFFFFFFu, m, 1));
            m = fmaxf(m, __shfl_xor_sync(0xFFFFFFFFu, m, 2));
            if ((lane & 3) == 0)
                srow[(wm + mt * 16 + (lane >> 2) + 8 * h) * 4 + (warp >> 1)] = m;
        }
    }
    __syncthreads();
    if (tid < BM) {
        float m = fmaxf(fmaxf(srow[tid * 4 + 0], srow[tid * 4 + 1]),
                        fmaxf(srow[tid * 4 + 2], srow[tid * 4 + 3]));
        g_tmax[(size_t)(m0 + tid) * NTILE + blockIdx.x] = (uint16_t)mono16f(m);
    }
}

// ---------------- select: threshold on tile maxes, scan only qualifying tiles ----------------
__global__ __launch_bounds__(256) void select_kernel() {
    const int q = blockIdx.x;
    const int t = threadIdx.x, lane = t & 31, warp = t >> 5;

    __shared__ uint32_t wf[8];
    __shared__ int      scnt;
    __shared__ uint16_t slist[NTILE];
    __shared__ uint32_t sw[256];

    // each thread owns 2 tile-maxes (tiles 2t, 2t+1); warp owns 64 consecutive tiles
    uint32_t w0 = ((const uint32_t*)(g_tmax + (size_t)q * NTILE))[t];
    uint32_t v0 = w0 & 0xFFFFu, v1 = w0 >> 16;
    uint32_t hi = max(v0, v1), lo = min(v0, v1);

    // warp's ~4th-largest (ties demote conservatively -> smaller T -> safe)
    uint32_t cur = hi, fourth = 0;
    #pragma unroll
    for (int r = 0; r < 4; r++) {
        uint32_t b = cur;
        #pragma unroll
        for (int o = 16; o; o >>= 1) b = max(b, __shfl_xor_sync(0xFFFFFFFFu, b, o));
        if (cur == b) { cur = lo; lo = 0; }
        fourth = b;
    }
    if (t == 0) scnt = 0;
    if (lane == 0) wf[warp] = fourth;
    __syncthreads();

    uint32_t T = wf[0];
    #pragma unroll
    for (int j = 1; j < 8; j++) T = min(T, wf[j]);

    // collect qualifying tiles (tmax >= T). >=32 qualify by construction.
    if (v0 >= T) { int p = atomicAdd(&scnt, 1); slist[p] = (uint16_t)(2 * t); }
    if (v1 >= T) { int p = atomicAdd(&scnt, 1); slist[p] = (uint16_t)(2 * t + 1); }
    __syncthreads();
    const int nq = scnt;

    // scan qualifying tiles: warp-per-tile, lane loads 4 bf16 (uint2, coalesced 256B)
    const uint32_t* rowp = (const uint32_t*)(g_S + (size_t)q * CC);
    uint32_t pk[8];
    #pragma unroll
    for (int j = 0; j < 8; j++) pk[j] = 0;

    for (int i = warp; i < nq; i += 8) {
        const int tile = slist[i];
        const uint32_t c0 = ((uint32_t)tile << 7) + ((uint32_t)lane << 2);
        uint2 d = *(const uint2*)&rowp[c0 >> 1];
        ins8(pk, (mono16b(d.x & 0xFFFFu) << 16) | ((c0    ) ^ 0xFFFFu));
        ins8(pk, (mono16b(d.x >> 16)     << 16) | ((c0 + 1) ^ 0xFFFFu));
        ins8(pk, (mono16b(d.y & 0xFFFFu) << 16) | ((c0 + 2) ^ 0xFFFFu));
        ins8(pk, (mono16b(d.y >> 16)     << 16) | ((c0 + 3) ^ 0xFFFFu));
    }

    // warp-local top-32 extraction; shift-based (constant indices only; pk unique)
    uint32_t keep = 0;
    for (int r = 0; r < KCAND; r++) {
        uint32_t my = pk[0];
        uint32_t b = my;
        #pragma unroll
        for (int o = 16; o; o >>= 1) b = max(b, __shfl_xor_sync(0xFFFFFFFFu, b, o));
        if (b != 0 && my == b) {
            #pragma unroll
            for (int j = 0; j < 7; j++) pk[j] = pk[j + 1];
            pk[7] = 0;
        }
        if (lane == r) keep = b;
    }
    sw[warp * 32 + lane] = keep;
    __syncthreads();

    // warp 0 merges 8x32 survivors -> final top-32
    if (warp == 0) {
        uint32_t k2[8];
        #pragma unroll
        for (int j = 0; j < 8; j++) k2[j] = sw[lane + (j << 5)];
        uint32_t keep2 = 0;
        for (int r = 0; r < KCAND; r++) {
            uint32_t b = 0;
            #pragma unroll
            for (int j = 0; j < 8; j++) b = max(b, k2[j]);
            #pragma unroll
            for (int o = 16; o; o >>= 1) b = max(b, __shfl_xor_sync(0xFFFFFFFFu, b, o));
            #pragma unroll
            for (int j = 0; j < 8; j++)
                if (k2[j] == b) k2[j] = 0;
            if (lane == r) keep2 = b;
        }
        g_cand[q * KCAND + lane] = (int)((keep2 & 0xFFFFu) ^ 0xFFFFu);
    }
}

// ---------------- usage init: out_usage = memory_usage ----------------
__global__ void usage_init_kernel(const float* __restrict__ u, float* __restrict__ out_u) {
    int i = blockIdx.x * blockDim.x + threadIdx.x;
    out_u[i] = u[i];
}

// ---------------- exact fp32 rescore of 32 candidates + top-8 + gather + counts ----------------
__global__ void rescore_gather_kernel(const float* __restrict__ q,
                                      const float* __restrict__ keys,
                                      const float* __restrict__ vals,
                                      float* __restrict__ out_k,
                                      float* __restrict__ out_v,
                                      float* __restrict__ out_u) {
    const int b = blockIdx.x;
    const int t = threadIdx.x, lane = t & 31, w = t >> 5;
    __shared__ float qs[DIM];
    __shared__ float simv[KCAND];
    __shared__ int   simi[KCAND];
    __shared__ int   topi[KSEL];

    ((float4*)qs)[t] = ((const float4*)(q + (size_t)b * DIM))[t];
    __syncthreads();

    #pragma unroll
    for (int jj = 0; jj < 4; jj++) {
        int j = w * 4 + jj;
        int c = g_cand[b * KCAND + j];
        const float* kr = keys + (size_t)c * DIM;
        float s = 0.f;
        #pragma unroll 8
        for (int i = lane; i < DIM; i += 32) s = fmaf(qs[i], kr[i], s);
        #pragma unroll
        for (int o = 16; o; o >>= 1) s += __shfl_xor_sync(0xFFFFFFFFu, s, o);
        if (lane == 0) { simv[j] = s * g_rnorm[c]; simi[j] = c; }
    }
    __syncthreads();

    if (t == 0) {
        unsigned used = 0;
        for (int r = 0; r < KSEL; r++) {
            int best = -1;
            for (int j = 0; j < KCAND; j++) {
                if (used & (1u << j)) continue;
                if (best < 0 || simv[j] > simv[best] ||
                    (simv[j] == simv[best] && simi[j] < simi[best])) best = j;
            }
            used |= 1u << best;
            topi[r] = simi[best];
        }
    }
    __syncthreads();

    for (int r = 0; r < KSEL; r++) {
        int c = topi[r];
        const float4* sk = (const float4*)(keys + (size_t)c * DIM);
        const float4* sv2 = (const float4*)(vals + (size_t)c * DIM);
        float4* dk = (float4*)(out_k + ((size_t)b * KSEL + r) * DIM);
        float4* dv = (float4*)(out_v + ((size_t)b * KSEL + r) * DIM);
        dk[t] = sk[t];
        dv[t] = sv2[t];
    }
    if (t < KSEL) atomicAdd(&out_u[topi[t]], 1.0f);
}

// ---------------- launch ----------------
extern "C" void kernel_launch(void* const* d_in, const int* in_sizes, int n_in,
                              void* d_out, int out_size) {
    const float* query  = (const float*)d_in[0];
    const float* keys   = (const float*)d_in[1];
    const float* values = (const float*)d_in[2];
    const float* usage  = (const float*)d_in[3];
    // d_in[4] = k (fixed to 8 by problem shape / out_size)

    float* out       = (float*)d_out;
    float* out_keys  = out;
    float* out_vals  = out + (size_t)BQ * KSEL * DIM;
    float* out_usage = out + (size_t)2 * BQ * KSEL * DIM;

    cudaFuncSetAttribute(gemm_kernel, cudaFuncAttributeMaxDynamicSharedMemorySize, SMEM_DYN);

    prep_q_kernel<<<(BQ * DIM / 4) / 256, 256>>>((const float4*)query);
    prep_keys_kernel<<<CC, 256>>>(keys);

    dim3 ggrid(CC / BN, BQ / BM);       // (512, 16)
    gemm_kernel<<<ggrid, 256, SMEM_DYN>>>();

    select_kernel<<<BQ, 256>>>();
    usage_init_kernel<<<CC / 256, 256>>>(usage, out_usage);
    rescore_gather_kernel<<<BQ, 256>>>(query, keys, values, out_keys, out_vals, out_usage);
}

// round 12
// speedup vs baseline: 1.3669x; 1.0214x over previous
#include <cuda_runtime.h>
#include <cuda_bf16.h>
#include <cuda_fp8.h>
#include <stdint.h>
#include <stddef.h>

#define DIM   1024
#define BQ    2048
#define CC    65536
#define KSEL  8
#define KCAND 32
#define NTILE (CC / 128)        // 512 col-tiles of width 128

// ---------------- fp8 GEMM geometry ----------------
#define BM 128
#define BN 128
#define BKB 64                  // 64 fp8 bytes of K per chunk
#define NCHUNK (DIM / BKB)      // 16
#define LDSB 80                 // smem row stride in bytes (64 + 16 pad)
#define STAGE_BYTES (2 * BM * LDSB)   // A + B : 20480 B
#define STAGES 4
#define SMEM_DYN (STAGES * STAGE_BYTES)   // 81920 (x2 CTAs = 160 KB <= 228 KB)

// ---------------- scratch (device globals; no allocations allowed) ----------------
static __device__ uint8_t       g_Qf8[(size_t)BQ * DIM];     // 2 MB   (raw query, e4m3)
static __device__ uint8_t       g_Kf8[(size_t)CC * DIM];     // 64 MB  (16*normalized keys, e4m3)
static __device__ float         g_rnorm[CC];                 // 256 KB
static __device__ __nv_bfloat16 g_S[(size_t)BQ * CC];        // 256 MB (bf16 sims, scaled)
static __device__ uint16_t      g_tmax[(size_t)BQ * NTILE];  // 2 MB   (per row/tile max, mono16)
static __device__ int           g_cand[BQ * KCAND];          // 256 KB

// ---------------- helpers ----------------
__device__ __forceinline__ void cp_async16(void* smem, const void* gmem) {
    uint32_t s = (uint32_t)__cvta_generic_to_shared(smem);
    asm volatile("cp.async.cg.shared.global [%0], [%1], 16;\n" :: "r"(s), "l"(gmem) : "memory");
}
#define CP_COMMIT() asm volatile("cp.async.commit_group;\n" ::: "memory")

// pack 4 floats -> 4 e4m3 bytes (byte i = x[i])
__device__ __forceinline__ uint32_t pack_e4m3x4(float x0, float x1, float x2, float x3) {
    uint16_t lo, hi;
    asm("cvt.rn.satfinite.e4m3x2.f32 %0, %1, %2;" : "=h"(lo) : "f"(x1), "f"(x0));
    asm("cvt.rn.satfinite.e4m3x2.f32 %0, %1, %2;" : "=h"(hi) : "f"(x3), "f"(x2));
    return (uint32_t)lo | ((uint32_t)hi << 16);
}

__device__ __forceinline__ void mma_e4m3(float* d, const uint32_t* a, const uint32_t* b) {
    asm volatile(
        "mma.sync.aligned.m16n8k32.row.col.f32.e4m3.e4m3.f32 "
        "{%0,%1,%2,%3}, {%4,%5,%6,%7}, {%8,%9}, {%0,%1,%2,%3};\n"
        : "+f"(d[0]), "+f"(d[1]), "+f"(d[2]), "+f"(d[3])
        : "r"(a[0]), "r"(a[1]), "r"(a[2]), "r"(a[3]), "r"(b[0]), "r"(b[1]));
}

// float -> bf16(rn) bits -> order-preserving uint16 (larger float => larger uint)
__device__ __forceinline__ uint32_t mono16f(float x) {
    uint16_t b = __bfloat16_as_ushort(__float2bfloat16(x));
    return (b & 0x8000u) ? (uint32_t)(uint16_t)~b : (uint32_t)(b | 0x8000u);
}
// bf16 raw bits -> order-preserving uint16 (same mapping as mono16f on stored values)
__device__ __forceinline__ uint32_t mono16b(uint32_t b) {
    return (b & 0x8000u) ? ((uint32_t)(uint16_t)~b) : (b | 0x8000u);
}

// insert into sorted-desc reg array v[8] (compile-time indices only; rare true branch)
__device__ __forceinline__ void ins8(uint32_t* v, uint32_t c) {
    if (c > v[7]) {
        v[7] = c;
        #pragma unroll
        for (int j = 7; j > 0; j--)
            if (v[j] > v[j - 1]) { uint32_t tv = v[j]; v[j] = v[j - 1]; v[j - 1] = tv; }
    }
}

// ---------------- prep: query -> e4m3 ----------------
__global__ void prep_q_kernel(const float4* __restrict__ q) {
    int i = blockIdx.x * blockDim.x + threadIdx.x;   // over BQ*DIM/4
    float4 v = q[i];
    ((uint32_t*)g_Qf8)[i] = pack_e4m3x4(v.x, v.y, v.z, v.w);
}

// ---------------- prep: keys -> 16 * normalized e4m3 + inverse norms ----------------
__global__ void prep_keys_kernel(const float* __restrict__ keys) {
    int row = blockIdx.x;
    int t = threadIdx.x, lane = t & 31, w = t >> 5;
    const float4* kr = (const float4*)(keys + (size_t)row * DIM);   // 256 float4 per row
    float4 v = kr[t];
    float ss = v.x*v.x + v.y*v.y + v.z*v.z + v.w*v.w;
    #pragma unroll
    for (int o = 16; o; o >>= 1) ss += __shfl_xor_sync(0xFFFFFFFFu, ss, o);
    __shared__ float sred[8];
    __shared__ float srn;
    if (lane == 0) sred[w] = ss;
    __syncthreads();
    if (t == 0) {
        float tot = 0.f;
        #pragma unroll
        for (int j = 0; j < 8; j++) tot += sred[j];
        float rn = 1.0f / fmaxf(sqrtf(tot), 1e-12f);
        g_rnorm[row] = rn;
        srn = rn * 16.0f;       // scale into e4m3 sweet spot (monotone per-column factor)
    }
    __syncthreads();
    float rn = srn;
    ((uint32_t*)(g_Kf8 + (size_t)row * DIM))[t] =
        pack_e4m3x4(v.x * rn, v.y * rn, v.z * rn, v.w * rn);
}

// ---------------- fp8 GEMM: S[b,c] = bf16( Qf8[b,:] . Kf8[c,:] ), + per-row tile max ----
// 4-stage cp.async pipeline, ONE __syncthreads per chunk, loads issued before compute.
__global__ __launch_bounds__(256, 2) void gemm_kernel() {
    extern __shared__ uint8_t smem[];

    const int tid = threadIdx.x;
    const int m0 = blockIdx.y * BM;
    const int n0 = blockIdx.x * BN;
    const int warp = tid >> 5, lane = tid & 31;
    const int wm = (warp & 1) * 64;     // 2 warps in M (64 rows each)
    const int wn = (warp >> 1) * 32;    // 4 warps in N (32 cols each)

    float acc[4][4][4];
    #pragma unroll
    for (int i = 0; i < 4; i++)
        #pragma unroll
        for (int j = 0; j < 4; j++)
            #pragma unroll
            for (int r = 0; r < 4; r++) acc[i][j][r] = 0.f;

    // stage layout: A rows [0,128) then B rows [0,128), each LDSB bytes
#define LOAD_CHUNK(st, kt) do {                                                        \
        uint8_t* base_ = smem + (st) * STAGE_BYTES;                                    \
        int kb_ = (kt) * BKB;                                                          \
        _Pragma("unroll")                                                              \
        for (int h = 0; h < 4; h++) {                                                  \
            int e_ = tid + (h << 8);          /* 0..1023 */                            \
            int row_ = e_ >> 2, seg_ = e_ & 3;                                         \
            const uint8_t* g_ = (row_ < BM)                                            \
                ? g_Qf8 + (((size_t)(m0 + row_)) << 10) + kb_ + (seg_ << 4)            \
                : g_Kf8 + (((size_t)(n0 + row_ - BM)) << 10) + kb_ + (seg_ << 4);      \
            cp_async16(base_ + row_ * LDSB + (seg_ << 4), g_);                         \
        }                                                                              \
        CP_COMMIT();                                                                   \
    } while (0)

    LOAD_CHUNK(0, 0);
    LOAD_CHUNK(1, 1);
    LOAD_CHUNK(2, 2);

    for (int kt = 0; kt < NCHUNK; kt++) {
        const int st = kt & 3;
        // wait for chunk kt to be resident (2/1/0 newer groups may stay pending)
        if (kt < NCHUNK - 2)       asm volatile("cp.async.wait_group 2;\n" ::: "memory");
        else if (kt == NCHUNK - 2) asm volatile("cp.async.wait_group 1;\n" ::: "memory");
        else                       asm volatile("cp.async.wait_group 0;\n" ::: "memory");
        // single barrier: publishes chunk kt AND guarantees chunk kt-1's compute is done,
        // freeing stage (kt-1)&3 == (kt+3)&3 for the prefetch below.
        __syncthreads();

        if (kt + 3 < NCHUNK) LOAD_CHUNK((kt + 3) & 3, kt + 3);

        const uint8_t* sA = smem + st * STAGE_BYTES;
        const uint8_t* sB = sA + BM * LDSB;

        #pragma unroll
        for (int ks = 0; ks < 2; ks++) {            // two k32 steps per 64B chunk
            const int kb = ks * 32;
            uint32_t a[4][4], bfr[4][2];
            #pragma unroll
            for (int mt = 0; mt < 4; mt++) {
                const uint8_t* p = sA + (wm + mt * 16 + (lane & 15)) * LDSB
                                      + kb + ((lane >> 4) << 4);
                uint32_t ad = (uint32_t)__cvta_generic_to_shared(p);
                asm volatile("ldmatrix.sync.aligned.m8n8.x4.shared.b16 {%0,%1,%2,%3}, [%4];\n"
                             : "=r"(a[mt][0]), "=r"(a[mt][1]), "=r"(a[mt][2]), "=r"(a[mt][3])
                             : "r"(ad));
            }
            #pragma unroll
            for (int np = 0; np < 2; np++) {        // 16 n-rows per x4
                const uint8_t* p = sB + (wn + np * 16 + (lane & 15)) * LDSB
                                      + kb + ((lane >> 4) << 4);
                uint32_t ad = (uint32_t)__cvta_generic_to_shared(p);
                uint32_t r0, r1, r2, r3;
                asm volatile("ldmatrix.sync.aligned.m8n8.x4.shared.b16 {%0,%1,%2,%3}, [%4];\n"
                             : "=r"(r0), "=r"(r1), "=r"(r2), "=r"(r3) : "r"(ad));
                bfr[np * 2][0]     = r0; bfr[np * 2][1]     = r2;
                bfr[np * 2 + 1][0] = r1; bfr[np * 2 + 1][1] = r3;
            }
            #pragma unroll
            for (int mt = 0; mt < 4; mt++)
                #pragma unroll
                for (int nt = 0; nt < 4; nt++)
                    mma_e4m3(acc[mt][nt], a[mt], bfr[nt]);
        }
    }
#undef LOAD_CHUNK

    // ---- epilogue 1: store bf16 sims ----
    #pragma unroll
    for (int mt = 0; mt < 4; mt++) {
        #pragma unroll
        for (int nt = 0; nt < 4; nt++) {
            int r0 = m0 + wm + mt * 16 + (lane >> 2);
            int cl = n0 + wn + nt * 8 + (lane & 3) * 2;
            size_t base = (size_t)r0 * CC + cl;
            *(__nv_bfloat162*)&g_S[base] =
                __floats2bfloat162_rn(acc[mt][nt][0], acc[mt][nt][1]);
            *(__nv_bfloat162*)&g_S[base + (size_t)8 * CC] =
                __floats2bfloat162_rn(acc[mt][nt][2], acc[mt][nt][3]);
        }
    }

    // ---- epilogue 2: per-row max over this CTA's 128 cols -> g_tmax (reduction only) ----
    __syncthreads();                    // compute finished everywhere; stages are dead
    float* srow = (float*)smem;         // [128][4] floats = 2 KB
    #pragma unroll
    for (int mt = 0; mt < 4; mt++) {
        #pragma unroll
        for (int h = 0; h < 2; h++) {   // h=0: row r0, h=1: row r0+8
            float m = fmaxf(acc[mt][0][2*h], acc[mt][0][2*h+1]);
            #pragma unroll
            for (int nt = 1; nt < 4; nt++)
                m = fmaxf(m, fmaxf(acc[mt][nt][2*h], acc[mt][nt][2*h+1]));
            // max over the 4 threads sharing this row (consecutive lanes)
            m = fmaxf(m, __shfl_xor_sync(0xFFFFFFFFu, m, 1));
            m = fmaxf(m, __shfl_xor_sync(0xFFFFFFFFu, m, 2));
            if ((lane & 3) == 0)
                srow[(wm + mt * 16 + (lane >> 2) + 8 * h) * 4 + (warp >> 1)] = m;
        }
    }
    __syncthreads();
    if (tid < BM) {
        float m = fmaxf(fmaxf(srow[tid * 4 + 0], srow[tid * 4 + 1]),
                        fmaxf(srow[tid * 4 + 2], srow[tid * 4 + 3]));
        g_tmax[(size_t)(m0 + tid) * NTILE + blockIdx.x] = (uint16_t)mono16f(m);
    }
}

// ---------------- select: threshold on tile maxes, scan only qualifying tiles ----------------
__global__ __launch_bounds__(256) void select_kernel() {
    const int q = blockIdx.x;
    const int t = threadIdx.x, lane = t & 31, warp = t >> 5;

    __shared__ uint32_t wf[8];
    __shared__ int      scnt;
    __shared__ uint16_t slist[NTILE];
    __shared__ uint32_t sw[256];

    // each thread owns 2 tile-maxes (tiles 2t, 2t+1); warp owns 64 consecutive tiles
    uint32_t w0 = ((const uint32_t*)(g_tmax + (size_t)q * NTILE))[t];
    uint32_t v0 = w0 & 0xFFFFu, v1 = w0 >> 16;
    uint32_t hi = max(v0, v1), lo = min(v0, v1);

    // warp's ~4th-largest (ties demote conservatively -> smaller T -> safe)
    uint32_t cur = hi, fourth = 0;
    #pragma unroll
    for (int r = 0; r < 4; r++) {
        uint32_t b = cur;
        #pragma unroll
        for (int o = 16; o; o >>= 1) b = max(b, __shfl_xor_sync(0xFFFFFFFFu, b, o));
        if (cur == b) { cur = lo; lo = 0; }
        fourth = b;
    }
    if (t == 0) scnt = 0;
    if (lane == 0) wf[warp] = fourth;
    __syncthreads();

    uint32_t T = wf[0];
    #pragma unroll
    for (int j = 1; j < 8; j++) T = min(T, wf[j]);

    // collect qualifying tiles (tmax >= T). >=32 qualify by construction.
    if (v0 >= T) { int p = atomicAdd(&scnt, 1); slist[p] = (uint16_t)(2 * t); }
    if (v1 >= T) { int p = atomicAdd(&scnt, 1); slist[p] = (uint16_t)(2 * t + 1); }
    __syncthreads();
    const int nq = scnt;

    // scan qualifying tiles: warp-per-tile, lane loads 4 bf16 (uint2, coalesced 256B)
    const uint32_t* rowp = (const uint32_t*)(g_S + (size_t)q * CC);
    uint32_t pk[8];
    #pragma unroll
    for (int j = 0; j < 8; j++) pk[j] = 0;

    for (int i = warp; i < nq; i += 8) {
        const int tile = slist[i];
        const uint32_t c0 = ((uint32_t)tile << 7) + ((uint32_t)lane << 2);
        uint2 d = *(const uint2*)&rowp[c0 >> 1];
        ins8(pk, (mono16b(d.x & 0xFFFFu) << 16) | ((c0    ) ^ 0xFFFFu));
        ins8(pk, (mono16b(d.x >> 16)     << 16) | ((c0 + 1) ^ 0xFFFFu));
        ins8(pk, (mono16b(d.y & 0xFFFFu) << 16) | ((c0 + 2) ^ 0xFFFFu));
        ins8(pk, (mono16b(d.y >> 16)     << 16) | ((c0 + 3) ^ 0xFFFFu));
    }

    // warp-local top-32 extraction; shift-based (constant indices only; pk unique)
    uint32_t keep = 0;
    for (int r = 0; r < KCAND; r++) {
        uint32_t my = pk[0];
        uint32_t b = my;
        #pragma unroll
        for (int o = 16; o; o >>= 1) b = max(b, __shfl_xor_sync(0xFFFFFFFFu, b, o));
        if (b != 0 && my == b) {
            #pragma unroll
            for (int j = 0; j < 7; j++) pk[j] = pk[j + 1];
            pk[7] = 0;
        }
        if (lane == r) keep = b;
    }
    sw[warp * 32 + lane] = keep;
    __syncthreads();

    // warp 0 merges 8x32 survivors -> final top-32
    if (warp == 0) {
        uint32_t k2[8];
        #pragma unroll
        for (int j = 0; j < 8; j++) k2[j] = sw[lane + (j << 5)];
        uint32_t keep2 = 0;
        for (int r = 0; r < KCAND; r++) {
            uint32_t b = 0;
            #pragma unroll
            for (int j = 0; j < 8; j++) b = max(b, k2[j]);
            #pragma unroll
            for (int o = 16; o; o >>= 1) b = max(b, __shfl_xor_sync(0xFFFFFFFFu, b, o));
            #pragma unroll
            for (int j = 0; j < 8; j++)
                if (k2[j] == b) k2[j] = 0;
            if (lane == r) keep2 = b;
        }
        g_cand[q * KCAND + lane] = (int)((keep2 & 0xFFFFu) ^ 0xFFFFu);
    }
}

// ---------------- usage init: out_usage = memory_usage ----------------
__global__ void usage_init_kernel(const float* __restrict__ u, float* __restrict__ out_u) {
    int i = blockIdx.x * blockDim.x + threadIdx.x;
    out_u[i] = u[i];
}

// ---------------- exact fp32 rescore of 32 candidates + top-8 + gather + counts ----------------
__global__ void rescore_gather_kernel(const float* __restrict__ q,
                                      const float* __restrict__ keys,
                                      const float* __restrict__ vals,
                                      float* __restrict__ out_k,
                                      float* __restrict__ out_v,
                                      float* __restrict__ out_u) {
    const int b = blockIdx.x;
    const int t = threadIdx.x, lane = t & 31, w = t >> 5;
    __shared__ float qs[DIM];
    __shared__ float simv[KCAND];
    __shared__ int   simi[KCAND];
    __shared__ int   topi[KSEL];

    ((float4*)qs)[t] = ((const float4*)(q + (size_t)b * DIM))[t];
    __syncthreads();

    #pragma unroll
    for (int jj = 0; jj < 4; jj++) {
        int j = w * 4 + jj;
        int c = g_cand[b * KCAND + j];
        const float* kr = keys + (size_t)c * DIM;
        float s = 0.f;
        #pragma unroll 8
        for (int i = lane; i < DIM; i += 32) s = fmaf(qs[i], kr[i], s);
        #pragma unroll
        for (int o = 16; o; o >>= 1) s += __shfl_xor_sync(0xFFFFFFFFu, s, o);
        if (lane == 0) { simv[j] = s * g_rnorm[c]; simi[j] = c; }
    }
    __syncthreads();

    if (t == 0) {
        unsigned used = 0;
        for (int r = 0; r < KSEL; r++) {
            int best = -1;
            for (int j = 0; j < KCAND; j++) {
                if (used & (1u << j)) continue;
                if (best < 0 || simv[j] > simv[best] ||
                    (simv[j] == simv[best] && simi[j] < simi[best])) best = j;
            }
            used |= 1u << best;
            topi[r] = simi[best];
        }
    }
    __syncthreads();

    for (int r = 0; r < KSEL; r++) {
        int c = topi[r];
        const float4* sk = (const float4*)(keys + (size_t)c * DIM);
        const float4* sv2 = (const float4*)(vals + (size_t)c * DIM);
        float4* dk = (float4*)(out_k + ((size_t)b * KSEL + r) * DIM);
        float4* dv = (float4*)(out_v + ((size_t)b * KSEL + r) * DIM);
        dk[t] = sk[t];
        dv[t] = sv2[t];
    }
    if (t < KSEL) atomicAdd(&out_u[topi[t]], 1.0f);
}

// ---------------- launch ----------------
extern "C" void kernel_launch(void* const* d_in, const int* in_sizes, int n_in,
                              void* d_out, int out_size) {
    const float* query  = (const float*)d_in[0];
    const float* keys   = (const float*)d_in[1];
    const float* values = (const float*)d_in[2];
    const float* usage  = (const float*)d_in[3];
    // d_in[4] = k (fixed to 8 by problem shape / out_size)

    float* out       = (float*)d_out;
    float* out_keys  = out;
    float* out_vals  = out + (size_t)BQ * KSEL * DIM;
    float* out_usage = out + (size_t)2 * BQ * KSEL * DIM;

    cudaFuncSetAttribute(gemm_kernel, cudaFuncAttributeMaxDynamicSharedMemorySize, SMEM_DYN);

    prep_q_kernel<<<(BQ * DIM / 4) / 256, 256>>>((const float4*)query);
    prep_keys_kernel<<<CC, 256>>>(keys);

    dim3 ggrid(CC / BN, BQ / BM);       // (512, 16)
    gemm_kernel<<<ggrid, 256, SMEM_DYN>>>();

    select_kernel<<<BQ, 256>>>();
    usage_init_kernel<<<CC / 256, 256>>>(usage, out_usage);
    rescore_gather_kernel<<<BQ, 256>>>(query, keys, values, out_keys, out_vals, out_usage);
}

// round 14
// speedup vs baseline: 1.5175x; 1.1102x over previous
#include <cuda_runtime.h>
#include <cuda_bf16.h>
#include <cuda_fp16.h>
#include <cuda_fp8.h>
#include <stdint.h>
#include <stddef.h>

#define DIM   1024
#define BQ    2048
#define CC    65536
#define KSEL  8
#define KCAND 32
#define NTILE (CC / 128)        // 512 col-tiles of width 128

// ---------------- fp8 GEMM geometry ----------------
#define BM 128
#define BN 128
#define BKB 128                 // 128 fp8 bytes of K per chunk (full row)
#define NCHUNK (DIM / BKB)      // 8
#define LDSB 144                // smem row stride (128 + 16 pad -> conflict-free ldmatrix)
#define STAGE_BYTES (2 * BM * LDSB)   // A + B : 36864 B
#define STAGES 3
#define SMEM_DYN (STAGES * STAGE_BYTES)   // 110592 (x2 CTAs = 221184 <= 228 KB)

// ---------------- scratch (device globals; no allocations allowed) ----------------
static __device__ uint8_t       g_Qf8[(size_t)BQ * DIM];     // 2 MB   (raw query, e4m3)
static __device__ uint8_t       g_Kf8[(size_t)CC * DIM];     // 64 MB  (16*normalized keys, e4m3)
static __device__ float         g_rnorm[CC];                 // 256 KB
static __device__ __nv_bfloat16 g_S[(size_t)BQ * CC];        // 256 MB (bf16 sims, scaled)
static __device__ uint16_t      g_tmax[(size_t)BQ * NTILE];  // 2 MB   (per row/tile max, mono16)
static __device__ int           g_cand[BQ * KCAND];          // 256 KB

// ---------------- helpers ----------------
__device__ __forceinline__ void cp_async16(void* smem, const void* gmem) {
    uint32_t s = (uint32_t)__cvta_generic_to_shared(smem);
    asm volatile("cp.async.cg.shared.global [%0], [%1], 16;\n" :: "r"(s), "l"(gmem) : "memory");
}
#define CP_COMMIT() asm volatile("cp.async.commit_group;\n" ::: "memory")

// pack 4 floats -> 4 e4m3 bytes (byte i = x[i])
__device__ __forceinline__ uint32_t pack_e4m3x4(float x0, float x1, float x2, float x3) {
    uint16_t lo, hi;
    asm("cvt.rn.satfinite.e4m3x2.f32 %0, %1, %2;" : "=h"(lo) : "f"(x1), "f"(x0));
    asm("cvt.rn.satfinite.e4m3x2.f32 %0, %1, %2;" : "=h"(hi) : "f"(x3), "f"(x2));
    return (uint32_t)lo | ((uint32_t)hi << 16);
}

// fp8 MMA with f16 accumulators: d/c are 2 regs = 4 f16 (same element map as f32 variant)
__device__ __forceinline__ void mma_e4m3_f16(uint32_t* d, const uint32_t* a, const uint32_t* b) {
    asm volatile(
        "mma.sync.aligned.m16n8k32.row.col.f16.e4m3.e4m3.f16 "
        "{%0,%1}, {%2,%3,%4,%5}, {%6,%7}, {%0,%1};\n"
        : "+r"(d[0]), "+r"(d[1])
        : "r"(a[0]), "r"(a[1]), "r"(a[2]), "r"(a[3]), "r"(b[0]), "r"(b[1]));
}

// float -> bf16(rn) bits -> order-preserving uint16 (larger float => larger uint)
__device__ __forceinline__ uint32_t mono16f(float x) {
    uint16_t b = __bfloat16_as_ushort(__float2bfloat16(x));
    return (b & 0x8000u) ? (uint32_t)(uint16_t)~b : (uint32_t)(b | 0x8000u);
}
// bf16 raw bits -> order-preserving uint16 (same mapping as mono16f on stored values)
__device__ __forceinline__ uint32_t mono16b(uint32_t b) {
    return (b & 0x8000u) ? ((uint32_t)(uint16_t)~b) : (b | 0x8000u);
}

// insert into sorted-desc reg array v[8] (compile-time indices only; rare true branch)
__device__ __forceinline__ void ins8(uint32_t* v, uint32_t c) {
    if (c > v[7]) {
        v[7] = c;
        #pragma unroll
        for (int j = 7; j > 0; j--)
            if (v[j] > v[j - 1]) { uint32_t tv = v[j]; v[j] = v[j - 1]; v[j - 1] = tv; }
    }
}

// ---------------- prep: query -> e4m3 ----------------
__global__ void prep_q_kernel(const float4* __restrict__ q) {
    int i = blockIdx.x * blockDim.x + threadIdx.x;   // over BQ*DIM/4
    float4 v = q[i];
    ((uint32_t*)g_Qf8)[i] = pack_e4m3x4(v.x, v.y, v.z, v.w);
}

// ---------------- prep: keys -> 16 * normalized e4m3 + inverse norms ----------------
__global__ void prep_keys_kernel(const float* __restrict__ keys) {
    int row = blockIdx.x;
    int t = threadIdx.x, lane = t & 31, w = t >> 5;
    const float4* kr = (const float4*)(keys + (size_t)row * DIM);   // 256 float4 per row
    float4 v = kr[t];
    float ss = v.x*v.x + v.y*v.y + v.z*v.z + v.w*v.w;
    #pragma unroll
    for (int o = 16; o; o >>= 1) ss += __shfl_xor_sync(0xFFFFFFFFu, ss, o);
    __shared__ float sred[8];
    __shared__ float srn;
    if (lane == 0) sred[w] = ss;
    __syncthreads();
    if (t == 0) {
        float tot = 0.f;
        #pragma unroll
        for (int j = 0; j < 8; j++) tot += sred[j];
        float rn = 1.0f / fmaxf(sqrtf(tot), 1e-12f);
        g_rnorm[row] = rn;
        srn = rn * 16.0f;       // scale into e4m3 sweet spot (monotone per-column factor)
    }
    __syncthreads();
    float rn = srn;
    ((uint32_t*)(g_Kf8 + (size_t)row * DIM))[t] =
        pack_e4m3x4(v.x * rn, v.y * rn, v.z * rn, v.w * rn);
}

// ---------------- fp8 GEMM (f16 acc): S = bf16( Qf8 . Kf8^T ), + per-row tile max ----
// 128B k-chunks, 3-stage cp.async pipeline, one __syncthreads per chunk.
__global__ __launch_bounds__(256, 2) void gemm_kernel() {
    extern __shared__ uint8_t smem[];

    const int tid = threadIdx.x;
    const int m0 = blockIdx.y * BM;
    const int n0 = blockIdx.x * BN;
    const int warp = tid >> 5, lane = tid & 31;
    const int wm = (warp & 1) * 64;     // 2 warps in M (64 rows each)
    const int wn = (warp >> 1) * 32;    // 4 warps in N (32 cols each)

    uint32_t acc[4][4][2];              // f16x2 accumulators
    #pragma unroll
    for (int i = 0; i < 4; i++)
        #pragma unroll
        for (int j = 0; j < 4; j++) { acc[i][j][0] = 0u; acc[i][j][1] = 0u; }

    // stage layout: A rows [0,128) then B rows [0,128), each LDSB bytes
#define LOAD_CHUNK(st, kt) do {                                                        \
        uint8_t* base_ = smem + (st) * STAGE_BYTES;                                    \
        int kb_ = (kt) * BKB;                                                          \
        _Pragma("unroll")                                                              \
        for (int h = 0; h < 8; h++) {                                                  \
            int e_ = tid + (h << 8);          /* 0..2047 */                            \
            int row_ = e_ >> 3, seg_ = e_ & 7;                                         \
            const uint8_t* g_ = (row_ < BM)                                            \
                ? g_Qf8 + (((size_t)(m0 + row_)) << 10) + kb_ + (seg_ << 4)            \
                : g_Kf8 + (((size_t)(n0 + row_ - BM)) << 10) + kb_ + (seg_ << 4);      \
            cp_async16(base_ + row_ * LDSB + (seg_ << 4), g_);                         \
        }                                                                              \
        CP_COMMIT();                                                                   \
    } while (0)

    LOAD_CHUNK(0, 0);
    LOAD_CHUNK(1, 1);

    for (int kt = 0; kt < NCHUNK; kt++) {
        const int st = kt % 3;
        // wait for chunk kt resident (the newer in-flight chunk may stay pending)
        if (kt < NCHUNK - 1) asm volatile("cp.async.wait_group 1;\n" ::: "memory");
        else                 asm volatile("cp.async.wait_group 0;\n" ::: "memory");
        // single barrier: publishes chunk kt AND frees stage (kt+2)%3 (chunk kt-1's)
        __syncthreads();

        if (kt + 2 < NCHUNK) LOAD_CHUNK((kt + 2) % 3, kt + 2);

        const uint8_t* sA = smem + st * STAGE_BYTES;
        const uint8_t* sB = sA + BM * LDSB;

        #pragma unroll
        for (int ks = 0; ks < 4; ks++) {            // four k32 steps per 128B chunk
            const int kb = ks * 32;
            uint32_t a[4][4], bfr[4][2];
            #pragma unroll
            for (int mt = 0; mt < 4; mt++) {
                const uint8_t* p = sA + (wm + mt * 16 + (lane & 15)) * LDSB
                                      + kb + ((lane >> 4) << 4);
                uint32_t ad = (uint32_t)__cvta_generic_to_shared(p);
                asm volatile("ldmatrix.sync.aligned.m8n8.x4.shared.b16 {%0,%1,%2,%3}, [%4];\n"
                             : "=r"(a[mt][0]), "=r"(a[mt][1]), "=r"(a[mt][2]), "=r"(a[mt][3])
                             : "r"(ad));
            }
            #pragma unroll
            for (int np = 0; np < 2; np++) {        // 16 n-rows per x4
                const uint8_t* p = sB + (wn + np * 16 + (lane & 15)) * LDSB
                                      + kb + ((lane >> 4) << 4);
                uint32_t ad = (uint32_t)__cvta_generic_to_shared(p);
                uint32_t r0, r1, r2, r3;
                asm volatile("ldmatrix.sync.aligned.m8n8.x4.shared.b16 {%0,%1,%2,%3}, [%4];\n"
                             : "=r"(r0), "=r"(r1), "=r"(r2), "=r"(r3) : "r"(ad));
                bfr[np * 2][0]     = r0; bfr[np * 2][1]     = r2;
                bfr[np * 2 + 1][0] = r1; bfr[np * 2 + 1][1] = r3;
            }
            #pragma unroll
            for (int mt = 0; mt < 4; mt++)
                #pragma unroll
                for (int nt = 0; nt < 4; nt++)
                    mma_e4m3_f16(acc[mt][nt], a[mt], bfr[nt]);
        }
    }
#undef LOAD_CHUNK

    // ---- epilogue 1: store bf16 sims (convert f16 acc -> f32 -> bf16) ----
    #pragma unroll
    for (int mt = 0; mt < 4; mt++) {
        #pragma unroll
        for (int nt = 0; nt < 4; nt++) {
            int r0 = m0 + wm + mt * 16 + (lane >> 2);
            int cl = n0 + wn + nt * 8 + (lane & 3) * 2;
            size_t base = (size_t)r0 * CC + cl;
            float2 a0 = __half22float2(*(const __half2*)&acc[mt][nt][0]);   // row r0
            float2 a1 = __half22float2(*(const __half2*)&acc[mt][nt][1]);   // row r0+8
            *(__nv_bfloat162*)&g_S[base] = __floats2bfloat162_rn(a0.x, a0.y);
            *(__nv_bfloat162*)&g_S[base + (size_t)8 * CC] = __floats2bfloat162_rn(a1.x, a1.y);
        }
    }

    // ---- epilogue 2: per-row max over this CTA's 128 cols -> g_tmax (reduction only) ----
    __syncthreads();                    // compute finished everywhere; stages are dead
    float* srow = (float*)smem;         // [128][4] floats = 2 KB
    #pragma unroll
    for (int mt = 0; mt < 4; mt++) {
        #pragma unroll
        for (int h = 0; h < 2; h++) {   // h=0: row r0, h=1: row r0+8
            __half2 hm = *(const __half2*)&acc[mt][0][h];
            #pragma unroll
            for (int nt = 1; nt < 4; nt++)
                hm = __hmax2(hm, *(const __half2*)&acc[mt][nt][h]);
            float2 fm = __half22float2(hm);
            float m = fmaxf(fm.x, fm.y);
            // max over the 4 threads sharing this row (consecutive lanes)
            m = fmaxf(m, __shfl_xor_sync(0xFFFFFFFFu, m, 1));
            m = fmaxf(m, __shfl_xor_sync(0xFFFFFFFFu, m, 2));
            if ((lane & 3) == 0)
                srow[(wm + mt * 16 + (lane >> 2) + 8 * h) * 4 + (warp >> 1)] = m;
        }
    }
    __syncthreads();
    if (tid < BM) {
        float m = fmaxf(fmaxf(srow[tid * 4 + 0], srow[tid * 4 + 1]),
                        fmaxf(srow[tid * 4 + 2], srow[tid * 4 + 3]));
        g_tmax[(size_t)(m0 + tid) * NTILE + blockIdx.x] = (uint16_t)mono16f(m);
    }
}

// ---------------- select: threshold on tile maxes, scan only qualifying tiles ----------------
__global__ __launch_bounds__(256) void select_kernel() {
    const int q = blockIdx.x;
    const int t = threadIdx.x, lane = t & 31, warp = t >> 5;

    __shared__ uint32_t wf[8];
    __shared__ int      scnt;
    __shared__ uint16_t slist[NTILE];
    __shared__ uint32_t sw[256];

    // each thread owns 2 tile-maxes (tiles 2t, 2t+1); warp owns 64 consecutive tiles
    uint32_t w0 = ((const uint32_t*)(g_tmax + (size_t)q * NTILE))[t];
    uint32_t v0 = w0 & 0xFFFFu, v1 = w0 >> 16;
    uint32_t hi = max(v0, v1), lo = min(v0, v1);

    // warp's ~4th-largest (ties demote conservatively -> smaller T -> safe)
    uint32_t cur = hi, fourth = 0;
    #pragma unroll
    for (int r = 0; r < 4; r++) {
        uint32_t b = cur;
        #pragma unroll
        for (int o = 16; o; o >>= 1) b = max(b, __shfl_xor_sync(0xFFFFFFFFu, b, o));
        if (cur == b) { cur = lo; lo = 0; }
        fourth = b;
    }
    if (t == 0) scnt = 0;
    if (lane == 0) wf[warp] = fourth;
    __syncthreads();

    uint32_t T = wf[0];
    #pragma unroll
    for (int j = 1; j < 8; j++) T = min(T, wf[j]);

    // collect qualifying tiles (tmax >= T). >=32 qualify by construction.
    if (v0 >= T) { int p = atomicAdd(&scnt, 1); slist[p] = (uint16_t)(2 * t); }
    if (v1 >= T) { int p = atomicAdd(&scnt, 1); slist[p] = (uint16_t)(2 * t + 1); }
    __syncthreads();
    const int nq = scnt;

    // scan qualifying tiles: warp-per-tile, lane loads 4 bf16 (uint2, coalesced 256B)
    const uint32_t* rowp = (const uint32_t*)(g_S + (size_t)q * CC);
    uint32_t pk[8];
    #pragma unroll
    for (int j = 0; j < 8; j++) pk[j] = 0;

    for (int i = warp; i < nq; i += 8) {
        const int tile = slist[i];
        const uint32_t c0 = ((uint32_t)tile << 7) + ((uint32_t)lane << 2);
        uint2 d = *(const uint2*)&rowp[c0 >> 1];
        ins8(pk, (mono16b(d.x & 0xFFFFu) << 16) | ((c0    ) ^ 0xFFFFu));
        ins8(pk, (mono16b(d.x >> 16)     << 16) | ((c0 + 1) ^ 0xFFFFu));
        ins8(pk, (mono16b(d.y & 0xFFFFu) << 16) | ((c0 + 2) ^ 0xFFFFu));
        ins8(pk, (mono16b(d.y >> 16)     << 16) | ((c0 + 3) ^ 0xFFFFu));
    }

    // warp-local top-32 extraction; shift-based (constant indices only; pk unique)
    uint32_t keep = 0;
    for (int r = 0; r < KCAND; r++) {
        uint32_t my = pk[0];
        uint32_t b = my;
        #pragma unroll
        for (int o = 16; o; o >>= 1) b = max(b, __shfl_xor_sync(0xFFFFFFFFu, b, o));
        if (b != 0 && my == b) {
            #pragma unroll
            for (int j = 0; j < 7; j++) pk[j] = pk[j + 1];
            pk[7] = 0;
        }
        if (lane == r) keep = b;
    }
    sw[warp * 32 + lane] = keep;
    __syncthreads();

    // warp 0 merges 8x32 survivors -> final top-32
    if (warp == 0) {
        uint32_t k2[8];
        #pragma unroll
        for (int j = 0; j < 8; j++) k2[j] = sw[lane + (j << 5)];
        uint32_t keep2 = 0;
        for (int r = 0; r < KCAND; r++) {
            uint32_t b = 0;
            #pragma unroll
            for (int j = 0; j < 8; j++) b = max(b, k2[j]);
            #pragma unroll
            for (int o = 16; o; o >>= 1) b = max(b, __shfl_xor_sync(0xFFFFFFFFu, b, o));
            #pragma unroll
            for (int j = 0; j < 8; j++)
                if (k2[j] == b) k2[j] = 0;
            if (lane == r) keep2 = b;
        }
        g_cand[q * KCAND + lane] = (int)((keep2 & 0xFFFFu) ^ 0xFFFFu);
    }
}

// ---------------- usage init: out_usage = memory_usage ----------------
__global__ void usage_init_kernel(const float* __restrict__ u, float* __restrict__ out_u) {
    int i = blockIdx.x * blockDim.x + threadIdx.x;
    out_u[i] = u[i];
}

// ---------------- exact fp32 rescore of 32 candidates + top-8 + gather + counts ----------------
__global__ void rescore_gather_kernel(const float* __restrict__ q,
                                      const float* __restrict__ keys,
                                      const float* __restrict__ vals,
                                      float* __restrict__ out_k,
                                      float* __restrict__ out_v,
                                      float* __restrict__ out_u) {
    const int b = blockIdx.x;
    const int t = threadIdx.x, lane = t & 31, w = t >> 5;
    __shared__ float qs[DIM];
    __shared__ float simv[KCAND];
    __shared__ int   simi[KCAND];
    __shared__ int   topi[KSEL];

    ((float4*)qs)[t] = ((const float4*)(q + (size_t)b * DIM))[t];
    __syncthreads();

    #pragma unroll
    for (int jj = 0; jj < 4; jj++) {
        int j = w * 4 + jj;
        int c = g_cand[b * KCAND + j];
        const float* kr = keys + (size_t)c * DIM;
        float s = 0.f;
        #pragma unroll 8
        for (int i = lane; i < DIM; i += 32) s = fmaf(qs[i], kr[i], s);
        #pragma unroll
        for (int o = 16; o; o >>= 1) s += __shfl_xor_sync(0xFFFFFFFFu, s, o);
        if (lane == 0) { simv[j] = s * g_rnorm[c]; simi[j] = c; }
    }
    __syncthreads();

    if (t == 0) {
        unsigned used = 0;
        for (int r = 0; r < KSEL; r++) {
            int best = -1;
            for (int j = 0; j < KCAND; j++) {
                if (used & (1u << j)) continue;
                if (best < 0 || simv[j] > simv[best] ||
                    (simv[j] == simv[best] && simi[j] < simi[best])) best = j;
            }
            used |= 1u << best;
            topi[r] = simi[best];
        }
    }
    __syncthreads();

    for (int r = 0; r < KSEL; r++) {
        int c = topi[r];
        const float4* sk = (const float4*)(keys + (size_t)c * DIM);
        const float4* sv2 = (const float4*)(vals + (size_t)c * DIM);
        float4* dk = (float4*)(out_k + ((size_t)b * KSEL + r) * DIM);
        float4* dv = (float4*)(out_v + ((size_t)b * KSEL + r) * DIM);
        dk[t] = sk[t];
        dv[t] = sv2[t];
    }
    if (t < KSEL) atomicAdd(&out_u[topi[t]], 1.0f);
}

// ---------------- launch ----------------
extern "C" void kernel_launch(void* const* d_in, const int* in_sizes, int n_in,
                              void* d_out, int out_size) {
    const float* query  = (const float*)d_in[0];
    const float* keys   = (const float*)d_in[1];
    const float* values = (const float*)d_in[2];
    const float* usage  = (const float*)d_in[3];
    // d_in[4] = k (fixed to 8 by problem shape / out_size)

    float* out       = (float*)d_out;
    float* out_keys  = out;
    float* out_vals  = out + (size_t)BQ * KSEL * DIM;
    float* out_usage = out + (size_t)2 * BQ * KSEL * DIM;

    cudaFuncSetAttribute(gemm_kernel, cudaFuncAttributeMaxDynamicSharedMemorySize, SMEM_DYN);

    prep_q_kernel<<<(BQ * DIM / 4) / 256, 256>>>((const float4*)query);
    prep_keys_kernel<<<CC, 256>>>(keys);

    dim3 ggrid(CC / BN, BQ / BM);       // (512, 16)
    gemm_kernel<<<ggrid, 256, SMEM_DYN>>>();

    select_kernel<<<BQ, 256>>>();
    usage_init_kernel<<<CC / 256, 256>>>(usage, out_usage);
    rescore_gather_kernel<<<BQ, 256>>>(query, keys, values, out_keys, out_vals, out_usage);
}

// round 15
// speedup vs baseline: 1.5471x; 1.0195x over previous
#include <cuda_runtime.h>
#include <cuda_bf16.h>
#include <cuda_fp16.h>
#include <cuda_fp8.h>
#include <stdint.h>
#include <stddef.h>

#define DIM   1024
#define BQ    2048
#define CC    65536
#define KSEL  8
#define KCAND 32
#define NTILE (CC / 128)        // 512 col-tiles of width 128

// ---------------- fp8 GEMM geometry ----------------
#define BM 128
#define BN 128
#define BKB 128                 // 128 fp8 bytes of K per chunk (full row)
#define NCHUNK (DIM / BKB)      // 8
#define LDSB 144                // smem row stride (128 + 16 pad -> conflict-free ldmatrix)
#define STAGE_BYTES (2 * BM * LDSB)   // A + B : 36864 B
#define STAGES 3
#define SMEM_DYN (STAGES * STAGE_BYTES)   // 110592 (x2 CTAs = 221184 <= 228 KB)
#define NTHREADS 128            // 4 warps; each warp owns a 64x64 output tile

// ---------------- scratch (device globals; no allocations allowed) ----------------
static __device__ uint8_t       g_Qf8[(size_t)BQ * DIM];     // 2 MB   (raw query, e4m3)
static __device__ uint8_t       g_Kf8[(size_t)CC * DIM];     // 64 MB  (16*normalized keys, e4m3)
static __device__ float         g_rnorm[CC];                 // 256 KB
static __device__ __nv_bfloat16 g_S[(size_t)BQ * CC];        // 256 MB (bf16 sims, scaled)
static __device__ uint16_t      g_tmax[(size_t)BQ * NTILE];  // 2 MB   (per row/tile max, mono16)
static __device__ int           g_cand[BQ * KCAND];          // 256 KB

// ---------------- helpers ----------------
__device__ __forceinline__ void cp_async16(void* smem, const void* gmem) {
    uint32_t s = (uint32_t)__cvta_generic_to_shared(smem);
    asm volatile("cp.async.cg.shared.global [%0], [%1], 16;\n" :: "r"(s), "l"(gmem) : "memory");
}
#define CP_COMMIT() asm volatile("cp.async.commit_group;\n" ::: "memory")

// pack 4 floats -> 4 e4m3 bytes (byte i = x[i])
__device__ __forceinline__ uint32_t pack_e4m3x4(float x0, float x1, float x2, float x3) {
    uint16_t lo, hi;
    asm("cvt.rn.satfinite.e4m3x2.f32 %0, %1, %2;" : "=h"(lo) : "f"(x1), "f"(x0));
    asm("cvt.rn.satfinite.e4m3x2.f32 %0, %1, %2;" : "=h"(hi) : "f"(x3), "f"(x2));
    return (uint32_t)lo | ((uint32_t)hi << 16);
}

// fp8 MMA with f16 accumulators: d/c are 2 regs = 4 f16 (same element map as f32 variant)
__device__ __forceinline__ void mma_e4m3_f16(uint32_t* d, const uint32_t* a, const uint32_t* b) {
    asm volatile(
        "mma.sync.aligned.m16n8k32.row.col.f16.e4m3.e4m3.f16 "
        "{%0,%1}, {%2,%3,%4,%5}, {%6,%7}, {%0,%1};\n"
        : "+r"(d[0]), "+r"(d[1])
        : "r"(a[0]), "r"(a[1]), "r"(a[2]), "r"(a[3]), "r"(b[0]), "r"(b[1]));
}

// float -> bf16(rn) bits -> order-preserving uint16 (larger float => larger uint)
__device__ __forceinline__ uint32_t mono16f(float x) {
    uint16_t b = __bfloat16_as_ushort(__float2bfloat16(x));
    return (b & 0x8000u) ? (uint32_t)(uint16_t)~b : (uint32_t)(b | 0x8000u);
}
// bf16 raw bits -> order-preserving uint16 (same mapping as mono16f on stored values)
__device__ __forceinline__ uint32_t mono16b(uint32_t b) {
    return (b & 0x8000u) ? ((uint32_t)(uint16_t)~b) : (b | 0x8000u);
}

// insert into sorted-desc reg array v[8] (compile-time indices only; rare true branch)
__device__ __forceinline__ void ins8(uint32_t* v, uint32_t c) {
    if (c > v[7]) {
        v[7] = c;
        #pragma unroll
        for (int j = 7; j > 0; j--)
            if (v[j] > v[j - 1]) { uint32_t tv = v[j]; v[j] = v[j - 1]; v[j - 1] = tv; }
    }
}

// ---------------- prep: query -> e4m3 ----------------
__global__ void prep_q_kernel(const float4* __restrict__ q) {
    int i = blockIdx.x * blockDim.x + threadIdx.x;   // over BQ*DIM/4
    float4 v = q[i];
    ((uint32_t*)g_Qf8)[i] = pack_e4m3x4(v.x, v.y, v.z, v.w);
}

// ---------------- prep: keys -> 16 * normalized e4m3 + inverse norms ----------------
__global__ void prep_keys_kernel(const float* __restrict__ keys) {
    int row = blockIdx.x;
    int t = threadIdx.x, lane = t & 31, w = t >> 5;
    const float4* kr = (const float4*)(keys + (size_t)row * DIM);   // 256 float4 per row
    float4 v = kr[t];
    float ss = v.x*v.x + v.y*v.y + v.z*v.z + v.w*v.w;
    #pragma unroll
    for (int o = 16; o; o >>= 1) ss += __shfl_xor_sync(0xFFFFFFFFu, ss, o);
    __shared__ float sred[8];
    __shared__ float srn;
    if (lane == 0) sred[w] = ss;
    __syncthreads();
    if (t == 0) {
        float tot = 0.f;
        #pragma unroll
        for (int j = 0; j < 8; j++) tot += sred[j];
        float rn = 1.0f / fmaxf(sqrtf(tot), 1e-12f);
        g_rnorm[row] = rn;
        srn = rn * 16.0f;       // scale into e4m3 sweet spot (monotone per-column factor)
    }
    __syncthreads();
    float rn = srn;
    ((uint32_t*)(g_Kf8 + (size_t)row * DIM))[t] =
        pack_e4m3x4(v.x * rn, v.y * rn, v.z * rn, v.w * rn);
}

// ---------------- fp8 GEMM (f16 acc): S = bf16( Qf8 . Kf8^T ), + per-row tile max ----
// 4 warps, 64x64 warp tiles: 32 MMA per 8 LDSM per k32 step.
__global__ __launch_bounds__(NTHREADS, 2) void gemm_kernel() {
    extern __shared__ uint8_t smem[];

    const int tid = threadIdx.x;
    const int m0 = blockIdx.y * BM;
    const int n0 = blockIdx.x * BN;
    const int warp = tid >> 5, lane = tid & 31;
    const int wm = (warp & 1) * 64;     // 2 warps in M (64 rows each)
    const int wn = (warp >> 1) * 64;    // 2 warps in N (64 cols each)

    uint32_t acc[4][8][2];              // f16x2 accumulators: 4 m16 x 8 n8 tiles
    #pragma unroll
    for (int i = 0; i < 4; i++)
        #pragma unroll
        for (int j = 0; j < 8; j++) { acc[i][j][0] = 0u; acc[i][j][1] = 0u; }

    // stage layout: A rows [0,128) then B rows [0,128), each LDSB bytes
#define LOAD_CHUNK(st, kt) do {                                                        \
        uint8_t* base_ = smem + (st) * STAGE_BYTES;                                    \
        int kb_ = (kt) * BKB;                                                          \
        _Pragma("unroll")                                                              \
        for (int h = 0; h < 16; h++) {                                                 \
            int e_ = tid + (h << 7);          /* 0..2047 */                            \
            int row_ = e_ >> 3, seg_ = e_ & 7;                                         \
            const uint8_t* g_ = (row_ < BM)                                            \
                ? g_Qf8 + (((size_t)(m0 + row_)) << 10) + kb_ + (seg_ << 4)            \
                : g_Kf8 + (((size_t)(n0 + row_ - BM)) << 10) + kb_ + (seg_ << 4);      \
            cp_async16(base_ + row_ * LDSB + (seg_ << 4), g_);                         \
        }                                                                              \
        CP_COMMIT();                                                                   \
    } while (0)

    LOAD_CHUNK(0, 0);
    LOAD_CHUNK(1, 1);

    for (int kt = 0; kt < NCHUNK; kt++) {
        const int st = kt % 3;
        // wait for chunk kt resident (the newer in-flight chunk may stay pending)
        if (kt < NCHUNK - 1) asm volatile("cp.async.wait_group 1;\n" ::: "memory");
        else                 asm volatile("cp.async.wait_group 0;\n" ::: "memory");
        // single barrier: publishes chunk kt AND frees stage (kt+2)%3 (chunk kt-1's)
        __syncthreads();

        if (kt + 2 < NCHUNK) LOAD_CHUNK((kt + 2) % 3, kt + 2);

        const uint8_t* sA = smem + st * STAGE_BYTES;
        const uint8_t* sB = sA + BM * LDSB;

        #pragma unroll
        for (int ks = 0; ks < 4; ks++) {            // four k32 steps per 128B chunk
            const int kb = ks * 32;
            uint32_t a[4][4], bfr[8][2];
            #pragma unroll
            for (int mt = 0; mt < 4; mt++) {
                const uint8_t* p = sA + (wm + mt * 16 + (lane & 15)) * LDSB
                                      + kb + ((lane >> 4) << 4);
                uint32_t ad = (uint32_t)__cvta_generic_to_shared(p);
                asm volatile("ldmatrix.sync.aligned.m8n8.x4.shared.b16 {%0,%1,%2,%3}, [%4];\n"
                             : "=r"(a[mt][0]), "=r"(a[mt][1]), "=r"(a[mt][2]), "=r"(a[mt][3])
                             : "r"(ad));
            }
            #pragma unroll
            for (int np = 0; np < 4; np++) {        // 64 n-rows = 4 x (16 rows per x4)
                const uint8_t* p = sB + (wn + np * 16 + (lane & 15)) * LDSB
                                      + kb + ((lane >> 4) << 4);
                uint32_t ad = (uint32_t)__cvta_generic_to_shared(p);
                uint32_t r0, r1, r2, r3;
                asm volatile("ldmatrix.sync.aligned.m8n8.x4.shared.b16 {%0,%1,%2,%3}, [%4];\n"
                             : "=r"(r0), "=r"(r1), "=r"(r2), "=r"(r3) : "r"(ad));
                bfr[np * 2][0]     = r0; bfr[np * 2][1]     = r2;
                bfr[np * 2 + 1][0] = r1; bfr[np * 2 + 1][1] = r3;
            }
            #pragma unroll
            for (int mt = 0; mt < 4; mt++)
                #pragma unroll
                for (int nt = 0; nt < 8; nt++)
                    mma_e4m3_f16(acc[mt][nt], a[mt], bfr[nt]);
        }
    }
#undef LOAD_CHUNK

    // ---- epilogue 1: store bf16 sims (convert f16 acc -> f32 -> bf16) ----
    #pragma unroll
    for (int mt = 0; mt < 4; mt++) {
        #pragma unroll
        for (int nt = 0; nt < 8; nt++) {
            int r0 = m0 + wm + mt * 16 + (lane >> 2);
            int cl = n0 + wn + nt * 8 + (lane & 3) * 2;
            size_t base = (size_t)r0 * CC + cl;
            float2 a0 = __half22float2(*(const __half2*)&acc[mt][nt][0]);   // row r0
            float2 a1 = __half22float2(*(const __half2*)&acc[mt][nt][1]);   // row r0+8
            *(__nv_bfloat162*)&g_S[base] = __floats2bfloat162_rn(a0.x, a0.y);
            *(__nv_bfloat162*)&g_S[base + (size_t)8 * CC] = __floats2bfloat162_rn(a1.x, a1.y);
        }
    }

    // ---- epilogue 2: per-row max over this CTA's 128 cols -> g_tmax (reduction only) ----
    __syncthreads();                    // compute finished everywhere; stages are dead
    float* srow = (float*)smem;         // [128][2] floats = 1 KB
    #pragma unroll
    for (int mt = 0; mt < 4; mt++) {
        #pragma unroll
        for (int h = 0; h < 2; h++) {   // h=0: row r0, h=1: row r0+8
            __half2 hm = *(const __half2*)&acc[mt][0][h];
            #pragma unroll
            for (int nt = 1; nt < 8; nt++)
                hm = __hmax2(hm, *(const __half2*)&acc[mt][nt][h]);
            float2 fm = __half22float2(hm);
            float m = fmaxf(fm.x, fm.y);
            // max over the 4 threads sharing this row (consecutive lanes)
            m = fmaxf(m, __shfl_xor_sync(0xFFFFFFFFu, m, 1));
            m = fmaxf(m, __shfl_xor_sync(0xFFFFFFFFu, m, 2));
            if ((lane & 3) == 0)
                srow[(wm + mt * 16 + (lane >> 2) + 8 * h) * 2 + (warp >> 1)] = m;
        }
    }
    __syncthreads();
    if (tid < BM) {
        float m = fmaxf(srow[tid * 2 + 0], srow[tid * 2 + 1]);
        g_tmax[(size_t)(m0 + tid) * NTILE + blockIdx.x] = (uint16_t)mono16f(m);
    }
}

// ---------------- select: threshold on tile maxes, scan only qualifying tiles ----------------
__global__ __launch_bounds__(256) void select_kernel() {
    const int q = blockIdx.x;
    const int t = threadIdx.x, lane = t & 31, warp = t >> 5;

    __shared__ uint32_t wf[8];
    __shared__ int      scnt;
    __shared__ uint16_t slist[NTILE];
    __shared__ uint32_t sw[256];

    // each thread owns 2 tile-maxes (tiles 2t, 2t+1); warp owns 64 consecutive tiles
    uint32_t w0 = ((const uint32_t*)(g_tmax + (size_t)q * NTILE))[t];
    uint32_t v0 = w0 & 0xFFFFu, v1 = w0 >> 16;
    uint32_t hi = max(v0, v1), lo = min(v0, v1);

    // warp's ~4th-largest (ties demote conservatively -> smaller T -> safe)
    uint32_t cur = hi, fourth = 0;
    #pragma unroll
    for (int r = 0; r < 4; r++) {
        uint32_t b = cur;
        #pragma unroll
        for (int o = 16; o; o >>= 1) b = max(b, __shfl_xor_sync(0xFFFFFFFFu, b, o));
        if (cur == b) { cur = lo; lo = 0; }
        fourth = b;
    }
    if (t == 0) scnt = 0;
    if (lane == 0) wf[warp] = fourth;
    __syncthreads();

    uint32_t T = wf[0];
    #pragma unroll
    for (int j = 1; j < 8; j++) T = min(T, wf[j]);

    // collect qualifying tiles (tmax >= T). >=32 qualify by construction.
    if (v0 >= T) { int p = atomicAdd(&scnt, 1); slist[p] = (uint16_t)(2 * t); }
    if (v1 >= T) { int p = atomicAdd(&scnt, 1); slist[p] = (uint16_t)(2 * t + 1); }
    __syncthreads();
    const int nq = scnt;

    // scan qualifying tiles: warp-per-tile, lane loads 4 bf16 (uint2, coalesced 256B)
    const uint32_t* rowp = (const uint32_t*)(g_S + (size_t)q * CC);
    uint32_t pk[8];
    #pragma unroll
    for (int j = 0; j < 8; j++) pk[j] = 0;

    for (int i = warp; i < nq; i += 8) {
        const int tile = slist[i];
        const uint32_t c0 = ((uint32_t)tile << 7) + ((uint32_t)lane << 2);
        uint2 d = *(const uint2*)&rowp[c0 >> 1];
        ins8(pk, (mono16b(d.x & 0xFFFFu) << 16) | ((c0    ) ^ 0xFFFFu));
        ins8(pk, (mono16b(d.x >> 16)     << 16) | ((c0 + 1) ^ 0xFFFFu));
        ins8(pk, (mono16b(d.y & 0xFFFFu) << 16) | ((c0 + 2) ^ 0xFFFFu));
        ins8(pk, (mono16b(d.y >> 16)     << 16) | ((c0 + 3) ^ 0xFFFFu));
    }

    // warp-local top-32 extraction; shift-based (constant indices only; pk unique)
    uint32_t keep = 0;
    for (int r = 0; r < KCAND; r++) {
        uint32_t my = pk[0];
        uint32_t b = my;
        #pragma unroll
        for (int o = 16; o; o >>= 1) b = max(b, __shfl_xor_sync(0xFFFFFFFFu, b, o));
        if (b != 0 && my == b) {
            #pragma unroll
            for (int j = 0; j < 7; j++) pk[j] = pk[j + 1];
            pk[7] = 0;
        }
        if (lane == r) keep = b;
    }
    sw[warp * 32 + lane] = keep;
    __syncthreads();

    // warp 0 merges 8x32 survivors -> final top-32
    if (warp == 0) {
        uint32_t k2[8];
        #pragma unroll
        for (int j = 0; j < 8; j++) k2[j] = sw[lane + (j << 5)];
        uint32_t keep2 = 0;
        for (int r = 0; r < KCAND; r++) {
            uint32_t b = 0;
            #pragma unroll
            for (int j = 0; j < 8; j++) b = max(b, k2[j]);
            #pragma unroll
            for (int o = 16; o; o >>= 1) b = max(b, __shfl_xor_sync(0xFFFFFFFFu, b, o));
            #pragma unroll
            for (int j = 0; j < 8; j++)
                if (k2[j] == b) k2[j] = 0;
            if (lane == r) keep2 = b;
        }
        g_cand[q * KCAND + lane] = (int)((keep2 & 0xFFFFu) ^ 0xFFFFu);
    }
}

// ---------------- usage init: out_usage = memory_usage ----------------
__global__ void usage_init_kernel(const float* __restrict__ u, float* __restrict__ out_u) {
    int i = blockIdx.x * blockDim.x + threadIdx.x;
    out_u[i] = u[i];
}

// ---------------- exact fp32 rescore of 32 candidates + top-8 + gather + counts ----------------
__global__ void rescore_gather_kernel(const float* __restrict__ q,
                                      const float* __restrict__ keys,
                                      const float* __restrict__ vals,
                                      float* __restrict__ out_k,
                                      float* __restrict__ out_v,
                                      float* __restrict__ out_u) {
    const int b = blockIdx.x;
    const int t = threadIdx.x, lane = t & 31, w = t >> 5;
    __shared__ float qs[DIM];
    __shared__ float simv[KCAND];
    __shared__ int   simi[KCAND];
    __shared__ int   topi[KSEL];

    ((float4*)qs)[t] = ((const float4*)(q + (size_t)b * DIM))[t];
    __syncthreads();

    #pragma unroll
    for (int jj = 0; jj < 4; jj++) {
        int j = w * 4 + jj;
        int c = g_cand[b * KCAND + j];
        const float* kr = keys + (size_t)c * DIM;
        float s = 0.f;
        #pragma unroll 8
        for (int i = lane; i < DIM; i += 32) s = fmaf(qs[i], kr[i], s);
        #pragma unroll
        for (int o = 16; o; o >>= 1) s += __shfl_xor_sync(0xFFFFFFFFu, s, o);
        if (lane == 0) { simv[j] = s * g_rnorm[c]; simi[j] = c; }
    }
    __syncthreads();

    if (t == 0) {
        unsigned used = 0;
        for (int r = 0; r < KSEL; r++) {
            int best = -1;
            for (int j = 0; j < KCAND; j++) {
                if (used & (1u << j)) continue;
                if (best < 0 || simv[j] > simv[best] ||
                    (simv[j] == simv[best] && simi[j] < simi[best])) best = j;
            }
            used |= 1u << best;
            topi[r] = simi[best];
        }
    }
    __syncthreads();

    for (int r = 0; r < KSEL; r++) {
        int c = topi[r];
        const float4* sk = (const float4*)(keys + (size_t)c * DIM);
        const float4* sv2 = (const float4*)(vals + (size_t)c * DIM);
        float4* dk = (float4*)(out_k + ((size_t)b * KSEL + r) * DIM);
        float4* dv = (float4*)(out_v + ((size_t)b * KSEL + r) * DIM);
        dk[t] = sk[t];
        dv[t] = sv2[t];
    }
    if (t < KSEL) atomicAdd(&out_u[topi[t]], 1.0f);
}

// ---------------- launch ----------------
extern "C" void kernel_launch(void* const* d_in, const int* in_sizes, int n_in,
                              void* d_out, int out_size) {
    const float* query  = (const float*)d_in[0];
    const float* keys   = (const float*)d_in[1];
    const float* values = (const float*)d_in[2];
    const float* usage  = (const float*)d_in[3];
    // d_in[4] = k (fixed to 8 by problem shape / out_size)

    float* out       = (float*)d_out;
    float* out_keys  = out;
    float* out_vals  = out + (size_t)BQ * KSEL * DIM;
    float* out_usage = out + (size_t)2 * BQ * KSEL * DIM;

    cudaFuncSetAttribute(gemm_kernel, cudaFuncAttributeMaxDynamicSharedMemorySize, SMEM_DYN);

    // usage_init moved BEFORE the GEMM (it is independent) so the GEMM is the
    // 4th launch — the slot the profiler has captured every round so far.
    prep_q_kernel<<<(BQ * DIM / 4) / 256, 256>>>((const float4*)query);
    prep_keys_kernel<<<CC, 256>>>(keys);
    usage_init_kernel<<<CC / 256, 256>>>(usage, out_usage);

    dim3 ggrid(CC / BN, BQ / BM);       // (512, 16)
    gemm_kernel<<<ggrid, NTHREADS, SMEM_DYN>>>();

    select_kernel<<<BQ, 256>>>();
    rescore_gather_kernel<<<BQ, 256>>>(query, keys, values, out_keys, out_vals, out_usage);
}

// round 16
// speedup vs baseline: 1.6494x; 1.0661x over previous
#include <cuda_runtime.h>
#include <cuda_bf16.h>
#include <cuda_fp16.h>
#include <cuda_fp8.h>
#include <stdint.h>
#include <stddef.h>

#define DIM   1024
#define BQ    2048
#define CC    65536
#define KSEL  8
#define KCAND 32
#define NTILE (CC / 128)        // 512 col-tiles of width 128

// ---------------- fp8 GEMM geometry ----------------
#define BM 128
#define BN 128
#define BKB 128                 // 128 fp8 bytes of K per chunk (full row)
#define NCHUNK (DIM / BKB)      // 8
#define LDSB 144                // smem row stride (128 + 16 pad -> conflict-free ldmatrix)
#define STAGE_BYTES (2 * BM * LDSB)   // A + B : 36864 B
#define STAGES 2
#define SMEM_DYN (STAGES * STAGE_BYTES)   // 73728 (x3 CTAs = 221184 <= 228 KB)
#define NTHREADS 128            // 4 warps; each warp owns a 64x64 output tile

// ---------------- scratch (device globals; no allocations allowed) ----------------
static __device__ uint8_t       g_Qf8[(size_t)BQ * DIM];     // 2 MB   (raw query, e4m3)
static __device__ uint8_t       g_Kf8[(size_t)CC * DIM];     // 64 MB  (16*normalized keys, e4m3)
static __device__ float         g_rnorm[CC];                 // 256 KB
static __device__ __nv_bfloat16 g_S[(size_t)BQ * CC];        // 256 MB (bf16 sims, scaled)
static __device__ uint16_t      g_tmax[(size_t)BQ * NTILE];  // 2 MB   (per row/tile max, mono16)
static __device__ int           g_cand[BQ * KCAND];          // 256 KB

// ---------------- helpers ----------------
__device__ __forceinline__ void cp_async16(void* smem, const void* gmem) {
    uint32_t s = (uint32_t)__cvta_generic_to_shared(smem);
    asm volatile("cp.async.cg.shared.global [%0], [%1], 16;\n" :: "r"(s), "l"(gmem) : "memory");
}
#define CP_COMMIT() asm volatile("cp.async.commit_group;\n" ::: "memory")

// pack 4 floats -> 4 e4m3 bytes (byte i = x[i])
__device__ __forceinline__ uint32_t pack_e4m3x4(float x0, float x1, float x2, float x3) {
    uint16_t lo, hi;
    asm("cvt.rn.satfinite.e4m3x2.f32 %0, %1, %2;" : "=h"(lo) : "f"(x1), "f"(x0));
    asm("cvt.rn.satfinite.e4m3x2.f32 %0, %1, %2;" : "=h"(hi) : "f"(x3), "f"(x2));
    return (uint32_t)lo | ((uint32_t)hi << 16);
}

// fp8 MMA with f16 accumulators: d/c are 2 regs = 4 f16 (same element map as f32 variant)
__device__ __forceinline__ void mma_e4m3_f16(uint32_t* d, const uint32_t* a, const uint32_t* b) {
    asm volatile(
        "mma.sync.aligned.m16n8k32.row.col.f16.e4m3.e4m3.f16 "
        "{%0,%1}, {%2,%3,%4,%5}, {%6,%7}, {%0,%1};\n"
        : "+r"(d[0]), "+r"(d[1])
        : "r"(a[0]), "r"(a[1]), "r"(a[2]), "r"(a[3]), "r"(b[0]), "r"(b[1]));
}

// float -> bf16(rn) bits -> order-preserving uint16 (larger float => larger uint)
__device__ __forceinline__ uint32_t mono16f(float x) {
    uint16_t b = __bfloat16_as_ushort(__float2bfloat16(x));
    return (b & 0x8000u) ? (uint32_t)(uint16_t)~b : (uint32_t)(b | 0x8000u);
}
// bf16 raw bits -> order-preserving uint16 (same mapping as mono16f on stored values)
__device__ __forceinline__ uint32_t mono16b(uint32_t b) {
    return (b & 0x8000u) ? ((uint32_t)(uint16_t)~b) : (b | 0x8000u);
}

// insert into sorted-desc reg array v[8] (compile-time indices only; rare true branch)
__device__ __forceinline__ void ins8(uint32_t* v, uint32_t c) {
    if (c > v[7]) {
        v[7] = c;
        #pragma unroll
        for (int j = 7; j > 0; j--)
            if (v[j] > v[j - 1]) { uint32_t tv = v[j]; v[j] = v[j - 1]; v[j - 1] = tv; }
    }
}

// ---------------- prep: query -> e4m3 ----------------
__global__ void prep_q_kernel(const float4* __restrict__ q) {
    int i = blockIdx.x * blockDim.x + threadIdx.x;   // over BQ*DIM/4
    float4 v = q[i];
    ((uint32_t*)g_Qf8)[i] = pack_e4m3x4(v.x, v.y, v.z, v.w);
}

// ---------------- prep: keys -> 16 * normalized e4m3 + inverse norms ----------------
__global__ void prep_keys_kernel(const float* __restrict__ keys) {
    int row = blockIdx.x;
    int t = threadIdx.x, lane = t & 31, w = t >> 5;
    const float4* kr = (const float4*)(keys + (size_t)row * DIM);   // 256 float4 per row
    float4 v = kr[t];
    float ss = v.x*v.x + v.y*v.y + v.z*v.z + v.w*v.w;
    #pragma unroll
    for (int o = 16; o; o >>= 1) ss += __shfl_xor_sync(0xFFFFFFFFu, ss, o);
    __shared__ float sred[8];
    __shared__ float srn;
    if (lane == 0) sred[w] = ss;
    __syncthreads();
    if (t == 0) {
        float tot = 0.f;
        #pragma unroll
        for (int j = 0; j < 8; j++) tot += sred[j];
        float rn = 1.0f / fmaxf(sqrtf(tot), 1e-12f);
        g_rnorm[row] = rn;
        srn = rn * 16.0f;       // scale into e4m3 sweet spot (monotone per-column factor)
    }
    __syncthreads();
    float rn = srn;
    ((uint32_t*)(g_Kf8 + (size_t)row * DIM))[t] =
        pack_e4m3x4(v.x * rn, v.y * rn, v.z * rn, v.w * rn);
}

// ---------------- fp8 GEMM (f16 acc): S = bf16( Qf8 . Kf8^T ), + per-row tile max ----
// 4 warps, 64x64 warp tiles, 2-stage pipeline, 3 CTAs/SM (regs capped at ~170).
__global__ __launch_bounds__(NTHREADS, 3) void gemm_kernel() {
    extern __shared__ uint8_t smem[];

    const int tid = threadIdx.x;
    const int m0 = blockIdx.y * BM;
    const int n0 = blockIdx.x * BN;
    const int warp = tid >> 5, lane = tid & 31;
    const int wm = (warp & 1) * 64;     // 2 warps in M (64 rows each)
    const int wn = (warp >> 1) * 64;    // 2 warps in N (64 cols each)

    uint32_t acc[4][8][2];              // f16x2 accumulators: 4 m16 x 8 n8 tiles
    #pragma unroll
    for (int i = 0; i < 4; i++)
        #pragma unroll
        for (int j = 0; j < 8; j++) { acc[i][j][0] = 0u; acc[i][j][1] = 0u; }

    // stage layout: A rows [0,128) then B rows [0,128), each LDSB bytes
#define LOAD_CHUNK(st, kt) do {                                                        \
        uint8_t* base_ = smem + (st) * STAGE_BYTES;                                    \
        int kb_ = (kt) * BKB;                                                          \
        _Pragma("unroll")                                                              \
        for (int h = 0; h < 16; h++) {                                                 \
            int e_ = tid + (h << 7);          /* 0..2047 */                            \
            int row_ = e_ >> 3, seg_ = e_ & 7;                                         \
            const uint8_t* g_ = (row_ < BM)                                            \
                ? g_Qf8 + (((size_t)(m0 + row_)) << 10) + kb_ + (seg_ << 4)            \
                : g_Kf8 + (((size_t)(n0 + row_ - BM)) << 10) + kb_ + (seg_ << 4);      \
            cp_async16(base_ + row_ * LDSB + (seg_ << 4), g_);                         \
        }                                                                              \
        CP_COMMIT();                                                                   \
    } while (0)

    LOAD_CHUNK(0, 0);

    for (int kt = 0; kt < NCHUNK; kt++) {
        const int st = kt & 1;
        // wait for chunk kt resident (only group kt can be pending here)
        asm volatile("cp.async.wait_group 0;\n" ::: "memory");
        // single barrier: publishes chunk kt AND guarantees chunk kt-1's compute is
        // done, freeing stage (kt+1)&1 for the prefetch below.
        __syncthreads();

        if (kt + 1 < NCHUNK) LOAD_CHUNK((kt + 1) & 1, kt + 1);

        const uint8_t* sA = smem + st * STAGE_BYTES;
        const uint8_t* sB = sA + BM * LDSB;

        #pragma unroll
        for (int ks = 0; ks < 4; ks++) {            // four k32 steps per 128B chunk
            const int kb = ks * 32;
            uint32_t a[4][4], bfr[8][2];
            #pragma unroll
            for (int mt = 0; mt < 4; mt++) {
                const uint8_t* p = sA + (wm + mt * 16 + (lane & 15)) * LDSB
                                      + kb + ((lane >> 4) << 4);
                uint32_t ad = (uint32_t)__cvta_generic_to_shared(p);
                asm volatile("ldmatrix.sync.aligned.m8n8.x4.shared.b16 {%0,%1,%2,%3}, [%4];\n"
                             : "=r"(a[mt][0]), "=r"(a[mt][1]), "=r"(a[mt][2]), "=r"(a[mt][3])
                             : "r"(ad));
            }
            #pragma unroll
            for (int np = 0; np < 4; np++) {        // 64 n-rows = 4 x (16 rows per x4)
                const uint8_t* p = sB + (wn + np * 16 + (lane & 15)) * LDSB
                                      + kb + ((lane >> 4) << 4);
                uint32_t ad = (uint32_t)__cvta_generic_to_shared(p);
                uint32_t r0, r1, r2, r3;
                asm volatile("ldmatrix.sync.aligned.m8n8.x4.shared.b16 {%0,%1,%2,%3}, [%4];\n"
                             : "=r"(r0), "=r"(r1), "=r"(r2), "=r"(r3) : "r"(ad));
                bfr[np * 2][0]     = r0; bfr[np * 2][1]     = r2;
                bfr[np * 2 + 1][0] = r1; bfr[np * 2 + 1][1] = r3;
            }
            #pragma unroll
            for (int mt = 0; mt < 4; mt++)
                #pragma unroll
                for (int nt = 0; nt < 8; nt++)
                    mma_e4m3_f16(acc[mt][nt], a[mt], bfr[nt]);
        }
    }
#undef LOAD_CHUNK

    // ---- epilogue 1: store bf16 sims (convert f16 acc -> f32 -> bf16) ----
    #pragma unroll
    for (int mt = 0; mt < 4; mt++) {
        #pragma unroll
        for (int nt = 0; nt < 8; nt++) {
            int r0 = m0 + wm + mt * 16 + (lane >> 2);
            int cl = n0 + wn + nt * 8 + (lane & 3) * 2;
            size_t base = (size_t)r0 * CC + cl;
            float2 a0 = __half22float2(*(const __half2*)&acc[mt][nt][0]);   // row r0
            float2 a1 = __half22float2(*(const __half2*)&acc[mt][nt][1]);   // row r0+8
            *(__nv_bfloat162*)&g_S[base] = __floats2bfloat162_rn(a0.x, a0.y);
            *(__nv_bfloat162*)&g_S[base + (size_t)8 * CC] = __floats2bfloat162_rn(a1.x, a1.y);
        }
    }

    // ---- epilogue 2: per-row max over this CTA's 128 cols -> g_tmax (reduction only) ----
    __syncthreads();                    // compute finished everywhere; stages are dead
    float* srow = (float*)smem;         // [128][2] floats = 1 KB
    #pragma unroll
    for (int mt = 0; mt < 4; mt++) {
        #pragma unroll
        for (int h = 0; h < 2; h++) {   // h=0: row r0, h=1: row r0+8
            __half2 hm = *(const __half2*)&acc[mt][0][h];
            #pragma unroll
            for (int nt = 1; nt < 8; nt++)
                hm = __hmax2(hm, *(const __half2*)&acc[mt][nt][h]);
            float2 fm = __half22float2(hm);
            float m = fmaxf(fm.x, fm.y);
            // max over the 4 threads sharing this row (consecutive lanes)
            m = fmaxf(m, __shfl_xor_sync(0xFFFFFFFFu, m, 1));
            m = fmaxf(m, __shfl_xor_sync(0xFFFFFFFFu, m, 2));
            if ((lane & 3) == 0)
                srow[(wm + mt * 16 + (lane >> 2) + 8 * h) * 2 + (warp >> 1)] = m;
        }
    }
    __syncthreads();
    if (tid < BM) {
        float m = fmaxf(srow[tid * 2 + 0], srow[tid * 2 + 1]);
        g_tmax[(size_t)(m0 + tid) * NTILE + blockIdx.x] = (uint16_t)mono16f(m);
    }
}

// ---------------- select: threshold on tile maxes, scan only qualifying tiles ----------------
__global__ __launch_bounds__(256) void select_kernel() {
    const int q = blockIdx.x;
    const int t = threadIdx.x, lane = t & 31, warp = t >> 5;

    __shared__ uint32_t wf[8];
    __shared__ int      scnt;
    __shared__ uint16_t slist[NTILE];
    __shared__ uint32_t sw[256];

    // each thread owns 2 tile-maxes (tiles 2t, 2t+1); warp owns 64 consecutive tiles
    uint32_t w0 = ((const uint32_t*)(g_tmax + (size_t)q * NTILE))[t];
    uint32_t v0 = w0 & 0xFFFFu, v1 = w0 >> 16;
    uint32_t hi = max(v0, v1), lo = min(v0, v1);

    // warp's ~4th-largest (ties demote conservatively -> smaller T -> safe)
    uint32_t cur = hi, fourth = 0;
    #pragma unroll
    for (int r = 0; r < 4; r++) {
        uint32_t b = cur;
        #pragma unroll
        for (int o = 16; o; o >>= 1) b = max(b, __shfl_xor_sync(0xFFFFFFFFu, b, o));
        if (cur == b) { cur = lo; lo = 0; }
        fourth = b;
    }
    if (t == 0) scnt = 0;
    if (lane == 0) wf[warp] = fourth;
    __syncthreads();

    uint32_t T = wf[0];
    #pragma unroll
    for (int j = 1; j < 8; j++) T = min(T, wf[j]);

    // collect qualifying tiles (tmax >= T). >=32 qualify by construction.
    if (v0 >= T) { int p = atomicAdd(&scnt, 1); slist[p] = (uint16_t)(2 * t); }
    if (v1 >= T) { int p = atomicAdd(&scnt, 1); slist[p] = (uint16_t)(2 * t + 1); }
    __syncthreads();
    const int nq = scnt;

    // scan qualifying tiles: warp-per-tile, lane loads 4 bf16 (uint2, coalesced 256B)
    const uint32_t* rowp = (const uint32_t*)(g_S + (size_t)q * CC);
    uint32_t pk[8];
    #pragma unroll
    for (int j = 0; j < 8; j++) pk[j] = 0;

    for (int i = warp; i < nq; i += 8) {
        const int tile = slist[i];
        const uint32_t c0 = ((uint32_t)tile << 7) + ((uint32_t)lane << 2);
        uint2 d = *(const uint2*)&rowp[c0 >> 1];
        ins8(pk, (mono16b(d.x & 0xFFFFu) << 16) | ((c0    ) ^ 0xFFFFu));
        ins8(pk, (mono16b(d.x >> 16)     << 16) | ((c0 + 1) ^ 0xFFFFu));
        ins8(pk, (mono16b(d.y & 0xFFFFu) << 16) | ((c0 + 2) ^ 0xFFFFu));
        ins8(pk, (mono16b(d.y >> 16)     << 16) | ((c0 + 3) ^ 0xFFFFu));
    }

    // warp-local top-32 extraction; shift-based (constant indices only; pk unique)
    uint32_t keep = 0;
    for (int r = 0; r < KCAND; r++) {
        uint32_t my = pk[0];
        uint32_t b = my;
        #pragma unroll
        for (int o = 16; o; o >>= 1) b = max(b, __shfl_xor_sync(0xFFFFFFFFu, b, o));
        if (b != 0 && my == b) {
            #pragma unroll
            for (int j = 0; j < 7; j++) pk[j] = pk[j + 1];
            pk[7] = 0;
        }
        if (lane == r) keep = b;
    }
    sw[warp * 32 + lane] = keep;
    __syncthreads();

    // warp 0 merges 8x32 survivors -> final top-32
    if (warp == 0) {
        uint32_t k2[8];
        #pragma unroll
        for (int j = 0; j < 8; j++) k2[j] = sw[lane + (j << 5)];
        uint32_t keep2 = 0;
        for (int r = 0; r < KCAND; r++) {
            uint32_t b = 0;
            #pragma unroll
            for (int j = 0; j < 8; j++) b = max(b, k2[j]);
            #pragma unroll
            for (int o = 16; o; o >>= 1) b = max(b, __shfl_xor_sync(0xFFFFFFFFu, b, o));
            #pragma unroll
            for (int j = 0; j < 8; j++)
                if (k2[j] == b) k2[j] = 0;
            if (lane == r) keep2 = b;
        }
        g_cand[q * KCAND + lane] = (int)((keep2 & 0xFFFFu) ^ 0xFFFFu);
    }
}

// ---------------- usage init: out_usage = memory_usage ----------------
__global__ void usage_init_kernel(const float* __restrict__ u, float* __restrict__ out_u) {
    int i = blockIdx.x * blockDim.x + threadIdx.x;
    out_u[i] = u[i];
}

// ---------------- exact fp32 rescore of 32 candidates + top-8 + gather + counts ----------------
__global__ void rescore_gather_kernel(const float* __restrict__ q,
                                      const float* __restrict__ keys,
                                      const float* __restrict__ vals,
                                      float* __restrict__ out_k,
                                      float* __restrict__ out_v,
                                      float* __restrict__ out_u) {
    const int b = blockIdx.x;
    const int t = threadIdx.x, lane = t & 31, w = t >> 5;
    __shared__ float qs[DIM];
    __shared__ float simv[KCAND];
    __shared__ int   simi[KCAND];
    __shared__ int   topi[KSEL];

    ((float4*)qs)[t] = ((const float4*)(q + (size_t)b * DIM))[t];
    __syncthreads();

    #pragma unroll
    for (int jj = 0; jj < 4; jj++) {
        int j = w * 4 + jj;
        int c = g_cand[b * KCAND + j];
        const float* kr = keys + (size_t)c * DIM;
        float s = 0.f;
        #pragma unroll 8
        for (int i = lane; i < DIM; i += 32) s = fmaf(qs[i], kr[i], s);
        #pragma unroll
        for (int o = 16; o; o >>= 1) s += __shfl_xor_sync(0xFFFFFFFFu, s, o);
        if (lane == 0) { simv[j] = s * g_rnorm[c]; simi[j] = c; }
    }
    __syncthreads();

    if (t == 0) {
        unsigned used = 0;
        for (int r = 0; r < KSEL; r++) {
            int best = -1;
            for (int j = 0; j < KCAND; j++) {
                if (used & (1u << j)) continue;
                if (best < 0 || simv[j] > simv[best] ||
                    (simv[j] == simv[best] && simi[j] < simi[best])) best = j;
            }
            used |= 1u << best;
            topi[r] = simi[best];
        }
    }
    __syncthreads();

    for (int r = 0; r < KSEL; r++) {
        int c = topi[r];
        const float4* sk = (const float4*)(keys + (size_t)c * DIM);
        const float4* sv2 = (const float4*)(vals + (size_t)c * DIM);
        float4* dk = (float4*)(out_k + ((size_t)b * KSEL + r) * DIM);
        float4* dv = (float4*)(out_v + ((size_t)b * KSEL + r) * DIM);
        dk[t] = sk[t];
        dv[t] = sv2[t];
    }
    if (t < KSEL) atomicAdd(&out_u[topi[t]], 1.0f);
}

// ---------------- launch ----------------
extern "C" void kernel_launch(void* const* d_in, const int* in_sizes, int n_in,
                              void* d_out, int out_size) {
    const float* query  = (const float*)d_in[0];
    const float* keys   = (const float*)d_in[1];
    const float* values = (const float*)d_in[2];
    const float* usage  = (const float*)d_in[3];
    // d_in[4] = k (fixed to 8 by problem shape / out_size)

    float* out       = (float*)d_out;
    float* out_keys  = out;
    float* out_vals  = out + (size_t)BQ * KSEL * DIM;
    float* out_usage = out + (size_t)2 * BQ * KSEL * DIM;

    cudaFuncSetAttribute(gemm_kernel, cudaFuncAttributeMaxDynamicSharedMemorySize, SMEM_DYN);

    // usage_init stays BEFORE the GEMM so the GEMM remains the 4th launch
    // (the slot the profiler captures).
    prep_q_kernel<<<(BQ * DIM / 4) / 256, 256>>>((const float4*)query);
    prep_keys_kernel<<<CC, 256>>>(keys);
    usage_init_kernel<<<CC / 256, 256>>>(usage, out_usage);

    dim3 ggrid(CC / BN, BQ / BM);       // (512, 16)
    gemm_kernel<<<ggrid, NTHREADS, SMEM_DYN>>>();

    select_kernel<<<BQ, 256>>>();
    rescore_gather_kernel<<<BQ, 256>>>(query, keys, values, out_keys, out_vals, out_usage);
}